// round 1
// baseline (speedup 1.0000x reference)
#include <cuda_runtime.h>
#include <cuda_bf16.h>
#include <math.h>

// Problem constants
#define B_  8
#define N_  2048
#define F_  256
#define ROWS (B_ * N_)            // 16384
#define OUT_ELEMS ((size_t)B_ * N_ * F_)   // 4,194,304

// Scratch (device globals — no allocation allowed)
__device__ float g_Wh[(size_t)B_ * N_ * F_];   // 16 MB
__device__ float g_e1[ROWS];
__device__ float g_e2[ROWS];

// ---------------------------------------------------------------------------
// Kernel 1: Wh = h @ W   (M=16384, K=256, Nc=256)  classic 64x64x16 SGEMM tile
// ---------------------------------------------------------------------------
#define BM 64
#define BN 64
#define BK 16

__global__ void k_gemm_wh(const float* __restrict__ h,
                          const float* __restrict__ W) {
    __shared__ float As[BK][BM];
    __shared__ float Bs[BK][BN];
    const int bx = blockIdx.x;   // N tile (0..3)
    const int by = blockIdx.y;   // M tile (0..255)
    const int tid = threadIdx.x;
    const int tx = tid & 15, ty = tid >> 4;

    float acc[4][4] = {};
    const int K = F_, Nc = F_;

    for (int k0 = 0; k0 < K; k0 += BK) {
        #pragma unroll
        for (int i = tid; i < BM * BK; i += 256) {
            int m = i / BK, k = i % BK;
            As[k][m] = h[(size_t)(by * BM + m) * K + k0 + k];
        }
        #pragma unroll
        for (int i = tid; i < BK * BN; i += 256) {
            int k = i / BN, n = i % BN;
            Bs[k][n] = W[(size_t)(k0 + k) * Nc + bx * BN + n];
        }
        __syncthreads();
        #pragma unroll
        for (int k = 0; k < BK; k++) {
            float a[4], b[4];
            #pragma unroll
            for (int i = 0; i < 4; i++) a[i] = As[k][ty * 4 + i];
            #pragma unroll
            for (int j = 0; j < 4; j++) b[j] = Bs[k][tx * 4 + j];
            #pragma unroll
            for (int i = 0; i < 4; i++)
                #pragma unroll
                for (int j = 0; j < 4; j++)
                    acc[i][j] = fmaf(a[i], b[j], acc[i][j]);
        }
        __syncthreads();
    }
    #pragma unroll
    for (int i = 0; i < 4; i++)
        #pragma unroll
        for (int j = 0; j < 4; j++)
            g_Wh[(size_t)(by * BM + ty * 4 + i) * Nc + bx * BN + tx * 4 + j] = acc[i][j];
}

// ---------------------------------------------------------------------------
// Kernel 2: e1[r] = Wh[r,:]·a[:F],  e2[r] = Wh[r,:]·a[F:]    one warp per row
// ---------------------------------------------------------------------------
__global__ void k_rowdots(const float* __restrict__ a) {
    const int gwarp = (blockIdx.x * blockDim.x + threadIdx.x) >> 5;
    const int lane = threadIdx.x & 31;
    if (gwarp >= ROWS) return;
    const float* row = g_Wh + (size_t)gwarp * F_;
    float s1 = 0.f, s2 = 0.f;
    #pragma unroll
    for (int f = lane; f < F_; f += 32) {
        float v = row[f];
        s1 = fmaf(v, a[f], s1);
        s2 = fmaf(v, a[F_ + f], s2);
    }
    #pragma unroll
    for (int o = 16; o; o >>= 1) {
        s1 += __shfl_xor_sync(0xffffffffu, s1, o);
        s2 += __shfl_xor_sync(0xffffffffu, s2, o);
    }
    if (lane == 0) { g_e1[gwarp] = s1; g_e2[gwarp] = s2; }
}

// ---------------------------------------------------------------------------
// Kernel 3: per-row masked leaky-relu + softmax -> attention (written to d_out)
// One block (256 threads) per (b,n) row; scores staged in smem.
// ---------------------------------------------------------------------------
__global__ void k_softmax(const int* __restrict__ adj,
                          float* __restrict__ att) {
    const int r = blockIdx.x;            // 0 .. ROWS-1
    const int b = r / N_;
    __shared__ float s[N_];
    __shared__ float red[256];

    const int* arow = adj + (size_t)r * N_;
    const float E1 = g_e1[r];
    const float* e2b = g_e2 + b * N_;

    float lmax = -INFINITY;
    for (int m = threadIdx.x; m < N_; m += 256) {
        float x = E1 + e2b[m];
        x = x > 0.f ? x : 0.2f * x;          // leaky relu, slope 0.2
        float sc = arow[m] > 0 ? x : -9e15f;
        s[m] = sc;
        lmax = fmaxf(lmax, sc);
    }
    red[threadIdx.x] = lmax;
    __syncthreads();
    #pragma unroll
    for (int o = 128; o; o >>= 1) {
        if (threadIdx.x < o) red[threadIdx.x] = fmaxf(red[threadIdx.x], red[threadIdx.x + o]);
        __syncthreads();
    }
    const float mx = red[0];
    __syncthreads();

    float lsum = 0.f;
    for (int m = threadIdx.x; m < N_; m += 256) {
        float ex = __expf(s[m] - mx);
        s[m] = ex;
        lsum += ex;
    }
    red[threadIdx.x] = lsum;
    __syncthreads();
    #pragma unroll
    for (int o = 128; o; o >>= 1) {
        if (threadIdx.x < o) red[threadIdx.x] += red[threadIdx.x + o];
        __syncthreads();
    }
    const float inv = 1.0f / red[0];

    float* orow = att + (size_t)r * N_;
    for (int m = threadIdx.x; m < N_; m += 256)
        orow[m] = s[m] * inv;
}

// ---------------------------------------------------------------------------
// Kernel 4: h_prime = attention @ Wh (per batch), out = h + elu(h_prime)
//   per batch: A [2048,2048] @ Bm [2048,256]
// ---------------------------------------------------------------------------
__global__ void k_gemm_av(const float* __restrict__ att,
                          const float* __restrict__ h,
                          float* __restrict__ out) {
    __shared__ float As[BK][BM];
    __shared__ float Bs[BK][BN];
    const int bz = blockIdx.z;   // batch
    const int bx = blockIdx.x;   // N tile (0..3)
    const int by = blockIdx.y;   // M tile (0..31)
    const int tid = threadIdx.x;
    const int tx = tid & 15, ty = tid >> 4;

    const float* A  = att + (size_t)bz * N_ * N_;
    const float* Bm = g_Wh + (size_t)bz * N_ * F_;

    float acc[4][4] = {};
    const int K = N_, Nc = F_;

    for (int k0 = 0; k0 < K; k0 += BK) {
        #pragma unroll
        for (int i = tid; i < BM * BK; i += 256) {
            int m = i / BK, k = i % BK;
            As[k][m] = A[(size_t)(by * BM + m) * K + k0 + k];
        }
        #pragma unroll
        for (int i = tid; i < BK * BN; i += 256) {
            int k = i / BN, n = i % BN;
            Bs[k][n] = Bm[(size_t)(k0 + k) * Nc + bx * BN + n];
        }
        __syncthreads();
        #pragma unroll
        for (int k = 0; k < BK; k++) {
            float a[4], b[4];
            #pragma unroll
            for (int i = 0; i < 4; i++) a[i] = As[k][ty * 4 + i];
            #pragma unroll
            for (int j = 0; j < 4; j++) b[j] = Bs[k][tx * 4 + j];
            #pragma unroll
            for (int i = 0; i < 4; i++)
                #pragma unroll
                for (int j = 0; j < 4; j++)
                    acc[i][j] = fmaf(a[i], b[j], acc[i][j]);
        }
        __syncthreads();
    }

    #pragma unroll
    for (int i = 0; i < 4; i++) {
        #pragma unroll
        for (int j = 0; j < 4; j++) {
            const int m = by * BM + ty * 4 + i;
            const int n = bx * BN + tx * 4 + j;
            const size_t idx = (size_t)bz * N_ * F_ + (size_t)m * F_ + n;
            float c = acc[i][j];
            float e = c > 0.f ? c : expm1f(c);   // elu, alpha=1
            out[idx] = h[idx] + e;
        }
    }
}

// ---------------------------------------------------------------------------
extern "C" void kernel_launch(void* const* d_in, const int* in_sizes, int n_in,
                              void* d_out, int out_size) {
    const float* h   = (const float*)d_in[0];
    const int*   adj = (const int*)  d_in[1];
    const float* W   = (const float*)d_in[2];
    const float* a   = (const float*)d_in[3];
    float* out = (float*)d_out;
    float* att = out + OUT_ELEMS;

    // 1. Wh = h @ W
    k_gemm_wh<<<dim3(F_ / BN, ROWS / BM), 256>>>(h, W);
    // 2. e1 / e2 row dots
    k_rowdots<<<ROWS / 8, 256>>>(a);
    // 3. masked softmax -> attention (directly into d_out)
    k_softmax<<<ROWS, 256>>>(adj, att);
    // 4. h_prime = attention @ Wh ; out = h + elu(h_prime)
    k_gemm_av<<<dim3(F_ / BN, N_ / BM, B_), 256>>>(att, h, out);
}

// round 2
// speedup vs baseline: 2.8317x; 2.8317x over previous
#include <cuda_runtime.h>
#include <cuda_bf16.h>
#include <math.h>
#include <stdint.h>

// Problem constants
#define B_  8
#define N_  2048
#define F_  256
#define ROWS (B_ * N_)            // 16384
#define OUT_ELEMS ((size_t)B_ * N_ * F_)   // 4,194,304

// Scratch (device globals — no allocation allowed)
__device__ float g_Wh[(size_t)B_ * N_ * F_];   // 16 MB
__device__ float g_e1[ROWS];
__device__ float g_e2[ROWS];

// ---------------------------------------------------------------------------
// Kernel 1: Wh = h @ W   (M=16384, K=256, Nc=256)  classic 64x64x16 SGEMM tile
// (fp32 on purpose: Wh feeds the softmax scores, which are checked at 1e-3)
// ---------------------------------------------------------------------------
#define BM 64
#define BN 64
#define BK 16

__global__ void k_gemm_wh(const float* __restrict__ h,
                          const float* __restrict__ W) {
    __shared__ float As[BK][BM];
    __shared__ float Bs[BK][BN];
    const int bx = blockIdx.x;   // N tile (0..3)
    const int by = blockIdx.y;   // M tile (0..255)
    const int tid = threadIdx.x;
    const int tx = tid & 15, ty = tid >> 4;

    float acc[4][4] = {};
    const int K = F_, Nc = F_;

    for (int k0 = 0; k0 < K; k0 += BK) {
        #pragma unroll
        for (int i = tid; i < BM * BK; i += 256) {
            int m = i / BK, k = i % BK;
            As[k][m] = h[(size_t)(by * BM + m) * K + k0 + k];
        }
        #pragma unroll
        for (int i = tid; i < BK * BN; i += 256) {
            int k = i / BN, n = i % BN;
            Bs[k][n] = W[(size_t)(k0 + k) * Nc + bx * BN + n];
        }
        __syncthreads();
        #pragma unroll
        for (int k = 0; k < BK; k++) {
            float a[4], b[4];
            #pragma unroll
            for (int i = 0; i < 4; i++) a[i] = As[k][ty * 4 + i];
            #pragma unroll
            for (int j = 0; j < 4; j++) b[j] = Bs[k][tx * 4 + j];
            #pragma unroll
            for (int i = 0; i < 4; i++)
                #pragma unroll
                for (int j = 0; j < 4; j++)
                    acc[i][j] = fmaf(a[i], b[j], acc[i][j]);
        }
        __syncthreads();
    }
    #pragma unroll
    for (int i = 0; i < 4; i++)
        #pragma unroll
        for (int j = 0; j < 4; j++)
            g_Wh[(size_t)(by * BM + ty * 4 + i) * Nc + bx * BN + tx * 4 + j] = acc[i][j];
}

// ---------------------------------------------------------------------------
// Kernel 2: e1[r] = Wh[r,:]·a[:F],  e2[r] = Wh[r,:]·a[F:]    one warp per row
// ---------------------------------------------------------------------------
__global__ void k_rowdots(const float* __restrict__ a) {
    const int gwarp = (blockIdx.x * blockDim.x + threadIdx.x) >> 5;
    const int lane = threadIdx.x & 31;
    if (gwarp >= ROWS) return;
    const float* row = g_Wh + (size_t)gwarp * F_;
    float s1 = 0.f, s2 = 0.f;
    #pragma unroll
    for (int f = lane; f < F_; f += 32) {
        float v = row[f];
        s1 = fmaf(v, a[f], s1);
        s2 = fmaf(v, a[F_ + f], s2);
    }
    #pragma unroll
    for (int o = 16; o; o >>= 1) {
        s1 += __shfl_xor_sync(0xffffffffu, s1, o);
        s2 += __shfl_xor_sync(0xffffffffu, s2, o);
    }
    if (lane == 0) { g_e1[gwarp] = s1; g_e2[gwarp] = s2; }
}

// ---------------------------------------------------------------------------
// Kernel 3: per-row masked leaky-relu + softmax -> attention (written to d_out)
// ---------------------------------------------------------------------------
__global__ void k_softmax(const int* __restrict__ adj,
                          float* __restrict__ att) {
    const int r = blockIdx.x;            // 0 .. ROWS-1
    const int b = r / N_;
    __shared__ float s[N_];
    __shared__ float red[256];

    const int* arow = adj + (size_t)r * N_;
    const float E1 = g_e1[r];
    const float* e2b = g_e2 + b * N_;

    float lmax = -INFINITY;
    for (int m = threadIdx.x; m < N_; m += 256) {
        float x = E1 + e2b[m];
        x = x > 0.f ? x : 0.2f * x;          // leaky relu, slope 0.2
        float sc = arow[m] > 0 ? x : -9e15f;
        s[m] = sc;
        lmax = fmaxf(lmax, sc);
    }
    red[threadIdx.x] = lmax;
    __syncthreads();
    #pragma unroll
    for (int o = 128; o; o >>= 1) {
        if (threadIdx.x < o) red[threadIdx.x] = fmaxf(red[threadIdx.x], red[threadIdx.x + o]);
        __syncthreads();
    }
    const float mx = red[0];
    __syncthreads();

    float lsum = 0.f;
    for (int m = threadIdx.x; m < N_; m += 256) {
        float ex = __expf(s[m] - mx);
        s[m] = ex;
        lsum += ex;
    }
    red[threadIdx.x] = lsum;
    __syncthreads();
    #pragma unroll
    for (int o = 128; o; o >>= 1) {
        if (threadIdx.x < o) red[threadIdx.x] += red[threadIdx.x + o];
        __syncthreads();
    }
    const float inv = 1.0f / red[0];

    float* orow = att + (size_t)r * N_;
    for (int m = threadIdx.x; m < N_; m += 256)
        orow[m] = s[m] * inv;
}

// ---------------------------------------------------------------------------
// Kernel 4 (NEW): h_prime = attention @ Wh via tf32 mma.sync tensor cores.
//   Per batch: A [2048,2048] @ B [2048,256].  Tile 128x128x32, 8 warps,
//   each warp 32x64 via 2x8 m16n8k8 fragments. Epilogue: out = h + elu.
// ---------------------------------------------------------------------------
__device__ __forceinline__ void mma_tf32(float* c, const uint32_t* a, const uint32_t* b) {
    asm volatile(
        "mma.sync.aligned.m16n8k8.row.col.f32.tf32.tf32.f32 "
        "{%0,%1,%2,%3}, {%4,%5,%6,%7}, {%8,%9}, {%0,%1,%2,%3};\n"
        : "+f"(c[0]), "+f"(c[1]), "+f"(c[2]), "+f"(c[3])
        : "r"(a[0]), "r"(a[1]), "r"(a[2]), "r"(a[3]), "r"(b[0]), "r"(b[1]));
}

#define ASTRIDE 36     // 32 + 4 : float4-aligned (144B), frag banks 4r+c distinct
#define BSTRIDE 136    // 128 + 8: float4-aligned (544B), frag banks 8k+n distinct

__global__ __launch_bounds__(256) void k_gemm_av_mma(const float* __restrict__ att,
                                                     const float* __restrict__ h,
                                                     float* __restrict__ out) {
    __shared__ float As[128][ASTRIDE];   // [m][k]
    __shared__ float Bs[32][BSTRIDE];    // [k][n]

    const int bz = blockIdx.z;   // batch
    const int bx = blockIdx.x;   // col tile of 128 (0..1)
    const int by = blockIdx.y;   // row tile of 128 (0..15)
    const int tid = threadIdx.x;
    const int lane = tid & 31;
    const int wid = tid >> 5;
    const int warp_m = wid & 3;      // 0..3  (rows, 32 each)
    const int warp_n = wid >> 2;     // 0..1  (cols, 64 each)
    const int gid = lane >> 2;       // 0..7
    const int tig = lane & 3;        // 0..3

    const float* A  = att  + (size_t)bz * N_ * N_ + (size_t)(by * 128) * N_;
    const float* Bg = g_Wh + (size_t)bz * N_ * F_ + bx * 128;

    float acc[2][8][4];
    #pragma unroll
    for (int mt = 0; mt < 2; mt++)
        #pragma unroll
        for (int j = 0; j < 8; j++)
            #pragma unroll
            for (int q = 0; q < 4; q++) acc[mt][j][q] = 0.f;

    // --- preload first K-tile ---
    #pragma unroll
    for (int i = 0; i < 4; i++) {
        int flat = tid + i * 256;            // float4 index
        int row = flat >> 3, c4 = flat & 7;  // 128 rows x 8 float4
        float4 v = *(const float4*)(A + (size_t)row * N_ + c4 * 4);
        *(float4*)&As[row][c4 * 4] = v;
    }
    #pragma unroll
    for (int i = 0; i < 4; i++) {
        int flat = tid + i * 256;
        int kr = flat >> 5, c4 = flat & 31;  // 32 rows x 32 float4
        float4 v = *(const float4*)(Bg + (size_t)kr * F_ + c4 * 4);
        *(float4*)&Bs[kr][c4 * 4] = v;
    }
    __syncthreads();

    float4 aN[4], bN[4];
    for (int k0 = 0; k0 < N_; k0 += 32) {
        const bool nxt = (k0 + 32) < N_;
        if (nxt) {
            #pragma unroll
            for (int i = 0; i < 4; i++) {
                int flat = tid + i * 256;
                int row = flat >> 3, c4 = flat & 7;
                aN[i] = *(const float4*)(A + (size_t)row * N_ + (k0 + 32) + c4 * 4);
            }
            #pragma unroll
            for (int i = 0; i < 4; i++) {
                int flat = tid + i * 256;
                int kr = flat >> 5, c4 = flat & 31;
                bN[i] = *(const float4*)(Bg + (size_t)(k0 + 32 + kr) * F_ + c4 * 4);
            }
        }

        #pragma unroll
        for (int kk = 0; kk < 32; kk += 8) {
            uint32_t afr[2][4];
            #pragma unroll
            for (int mt = 0; mt < 2; mt++) {
                int r = warp_m * 32 + mt * 16 + gid;
                afr[mt][0] = __float_as_uint(As[r    ][kk + tig    ]);
                afr[mt][1] = __float_as_uint(As[r + 8][kk + tig    ]);
                afr[mt][2] = __float_as_uint(As[r    ][kk + tig + 4]);
                afr[mt][3] = __float_as_uint(As[r + 8][kk + tig + 4]);
            }
            uint32_t bfr[8][2];
            #pragma unroll
            for (int j = 0; j < 8; j++) {
                int n = warp_n * 64 + j * 8 + gid;
                bfr[j][0] = __float_as_uint(Bs[kk + tig    ][n]);
                bfr[j][1] = __float_as_uint(Bs[kk + tig + 4][n]);
            }
            #pragma unroll
            for (int mt = 0; mt < 2; mt++)
                #pragma unroll
                for (int j = 0; j < 8; j++)
                    mma_tf32(acc[mt][j], afr[mt], bfr[j]);
        }
        __syncthreads();
        if (nxt) {
            #pragma unroll
            for (int i = 0; i < 4; i++) {
                int flat = tid + i * 256;
                int row = flat >> 3, c4 = flat & 7;
                *(float4*)&As[row][c4 * 4] = aN[i];
            }
            #pragma unroll
            for (int i = 0; i < 4; i++) {
                int flat = tid + i * 256;
                int kr = flat >> 5, c4 = flat & 31;
                *(float4*)&Bs[kr][c4 * 4] = bN[i];
            }
            __syncthreads();
        }
    }

    // --- epilogue: out = h + elu(h_prime) ---
    const size_t base = (size_t)bz * N_ * F_;
    #pragma unroll
    for (int mt = 0; mt < 2; mt++) {
        #pragma unroll
        for (int j = 0; j < 8; j++) {
            const int m0 = by * 128 + warp_m * 32 + mt * 16 + gid;
            const int n  = bx * 128 + warp_n * 64 + j * 8 + tig * 2;
            {
                const size_t idx = base + (size_t)m0 * F_ + n;
                float c0 = acc[mt][j][0], c1 = acc[mt][j][1];
                float e0 = c0 > 0.f ? c0 : expm1f(c0);
                float e1 = c1 > 0.f ? c1 : expm1f(c1);
                float2 hv = *(const float2*)(h + idx);
                float2 o = make_float2(hv.x + e0, hv.y + e1);
                *(float2*)(out + idx) = o;
            }
            {
                const size_t idx = base + (size_t)(m0 + 8) * F_ + n;
                float c2 = acc[mt][j][2], c3 = acc[mt][j][3];
                float e2 = c2 > 0.f ? c2 : expm1f(c2);
                float e3 = c3 > 0.f ? c3 : expm1f(c3);
                float2 hv = *(const float2*)(h + idx);
                float2 o = make_float2(hv.x + e2, hv.y + e3);
                *(float2*)(out + idx) = o;
            }
        }
    }
}

// ---------------------------------------------------------------------------
extern "C" void kernel_launch(void* const* d_in, const int* in_sizes, int n_in,
                              void* d_out, int out_size) {
    const float* h   = (const float*)d_in[0];
    const int*   adj = (const int*)  d_in[1];
    const float* W   = (const float*)d_in[2];
    const float* a   = (const float*)d_in[3];
    float* out = (float*)d_out;
    float* att = out + OUT_ELEMS;

    // 1. Wh = h @ W
    k_gemm_wh<<<dim3(F_ / BN, ROWS / BM), 256>>>(h, W);
    // 2. e1 / e2 row dots
    k_rowdots<<<ROWS / 8, 256>>>(a);
    // 3. masked softmax -> attention (directly into d_out)
    k_softmax<<<ROWS, 256>>>(adj, att);
    // 4. h_prime = attention @ Wh (tensor cores) ; out = h + elu(h_prime)
    k_gemm_av_mma<<<dim3(2, N_ / 128, B_), 256>>>(att, h, out);
}

// round 3
// speedup vs baseline: 4.5280x; 1.5991x over previous
#include <cuda_runtime.h>
#include <cuda_bf16.h>
#include <math.h>
#include <stdint.h>

// Problem constants
#define B_  8
#define N_  2048
#define F_  256
#define ROWS (B_ * N_)            // 16384
#define OUT_ELEMS ((size_t)B_ * N_ * F_)   // 4,194,304

// Scratch (device globals — no allocation allowed)
__device__ float g_Wh[(size_t)B_ * N_ * F_];   // 16 MB
__device__ __align__(16) float g_e1[ROWS];
__device__ __align__(16) float g_e2[ROWS];

// ---------------------------------------------------------------------------
// Shared MMA / cp.async helpers
// ---------------------------------------------------------------------------
__device__ __forceinline__ void mma_tf32(float* c, const uint32_t* a, const uint32_t* b) {
    asm volatile(
        "mma.sync.aligned.m16n8k8.row.col.f32.tf32.tf32.f32 "
        "{%0,%1,%2,%3}, {%4,%5,%6,%7}, {%8,%9}, {%0,%1,%2,%3};\n"
        : "+f"(c[0]), "+f"(c[1]), "+f"(c[2]), "+f"(c[3])
        : "r"(a[0]), "r"(a[1]), "r"(a[2]), "r"(a[3]), "r"(b[0]), "r"(b[1]));
}

__device__ __forceinline__ void split_tf32(float x, uint32_t& hi, uint32_t& lo) {
    uint32_t h_;
    asm("cvt.rna.tf32.f32 %0, %1;" : "=r"(h_) : "f"(x));
    float l = x - __uint_as_float(h_);
    uint32_t l_;
    asm("cvt.rna.tf32.f32 %0, %1;" : "=r"(l_) : "f"(l));
    hi = h_; lo = l_;
}

__device__ __forceinline__ void cp16(void* dst, const void* src) {
    uint32_t d = (uint32_t)__cvta_generic_to_shared(dst);
    asm volatile("cp.async.cg.shared.global [%0], [%1], 16;\n" :: "r"(d), "l"(src));
}
__device__ __forceinline__ void cp_commit() {
    asm volatile("cp.async.commit_group;\n");
}
template<int NPEND> __device__ __forceinline__ void cp_wait() {
    asm volatile("cp.async.wait_group %0;\n" :: "n"(NPEND));
}

// Dynamic smem stage layout: As 128x36 floats, then Bs 32x136 floats
#define STAGE_FLOATS 8960           // 4608 + 4352
#define A_OFF 0
#define B_OFF 4608
#define SMEM_BYTES (2 * STAGE_FLOATS * 4)   // 71680

// ---------------------------------------------------------------------------
// Kernel 1: Wh = h @ W via 3xTF32 split-precision tensor-core GEMM.
//   M=16384, Nc=256, K=256. Tile 128x128x32, cp.async double-buffered.
//   Error ~2^-21: safe for the softmax-score path (checked at 1e-3).
// ---------------------------------------------------------------------------
__global__ __launch_bounds__(256, 2) void k_gemm_wh_mma(const float* __restrict__ h,
                                                        const float* __restrict__ W) {
    extern __shared__ float dsm[];
    const int bx = blockIdx.x;   // 0..1
    const int by = blockIdx.y;   // 0..127
    const int tid = threadIdx.x;
    const int lane = tid & 31, wid = tid >> 5;
    const int warp_m = wid & 3, warp_n = wid >> 2;
    const int gid = lane >> 2, tig = lane & 3;

    const float* A  = h + (size_t)(by * 128) * F_;
    const float* Bg = W + bx * 128;

    float acc[2][8][4];
    #pragma unroll
    for (int mt = 0; mt < 2; mt++)
        #pragma unroll
        for (int j = 0; j < 8; j++)
            #pragma unroll
            for (int q = 0; q < 4; q++) acc[mt][j][q] = 0.f;

    // prologue: stage 0
    {
        float* As = dsm + A_OFF;
        float* Bs = dsm + B_OFF;
        #pragma unroll
        for (int i = 0; i < 4; i++) {
            int flat = tid + i * 256, row = flat >> 3, c4 = flat & 7;
            cp16(&As[row * 36 + c4 * 4], A + (size_t)row * F_ + c4 * 4);
        }
        #pragma unroll
        for (int i = 0; i < 4; i++) {
            int flat = tid + i * 256, kr = flat >> 5, c4 = flat & 31;
            cp16(&Bs[kr * 136 + c4 * 4], Bg + (size_t)kr * F_ + c4 * 4);
        }
        cp_commit();
    }

    const int NT = F_ / 32;   // 8
    for (int kt = 0; kt < NT; kt++) {
        const int cur = kt & 1;
        if (kt + 1 < NT) {
            const int k0 = (kt + 1) * 32;
            float* As = dsm + (1 - cur) * STAGE_FLOATS + A_OFF;
            float* Bs = dsm + (1 - cur) * STAGE_FLOATS + B_OFF;
            #pragma unroll
            for (int i = 0; i < 4; i++) {
                int flat = tid + i * 256, row = flat >> 3, c4 = flat & 7;
                cp16(&As[row * 36 + c4 * 4], A + (size_t)row * F_ + k0 + c4 * 4);
            }
            #pragma unroll
            for (int i = 0; i < 4; i++) {
                int flat = tid + i * 256, kr = flat >> 5, c4 = flat & 31;
                cp16(&Bs[kr * 136 + c4 * 4], Bg + (size_t)(k0 + kr) * F_ + c4 * 4);
            }
            cp_commit();
            cp_wait<1>();
        } else {
            cp_wait<0>();
        }
        __syncthreads();

        const float* As = dsm + cur * STAGE_FLOATS + A_OFF;
        const float* Bs = dsm + cur * STAGE_FLOATS + B_OFF;

        #pragma unroll
        for (int kk = 0; kk < 32; kk += 8) {
            uint32_t ah[2][4], al[2][4];
            #pragma unroll
            for (int mt = 0; mt < 2; mt++) {
                int r = warp_m * 32 + mt * 16 + gid;
                split_tf32(As[ r      * 36 + kk + tig    ], ah[mt][0], al[mt][0]);
                split_tf32(As[(r + 8) * 36 + kk + tig    ], ah[mt][1], al[mt][1]);
                split_tf32(As[ r      * 36 + kk + tig + 4], ah[mt][2], al[mt][2]);
                split_tf32(As[(r + 8) * 36 + kk + tig + 4], ah[mt][3], al[mt][3]);
            }
            uint32_t bh[8][2], bl[8][2];
            #pragma unroll
            for (int j = 0; j < 8; j++) {
                int n = warp_n * 64 + j * 8 + gid;
                split_tf32(Bs[(kk + tig    ) * 136 + n], bh[j][0], bl[j][0]);
                split_tf32(Bs[(kk + tig + 4) * 136 + n], bh[j][1], bl[j][1]);
            }
            #pragma unroll
            for (int mt = 0; mt < 2; mt++)
                #pragma unroll
                for (int j = 0; j < 8; j++) {
                    mma_tf32(acc[mt][j], ah[mt], bh[j]);
                    mma_tf32(acc[mt][j], al[mt], bh[j]);
                    mma_tf32(acc[mt][j], ah[mt], bl[j]);
                }
        }
        __syncthreads();
    }

    // epilogue: plain store to g_Wh
    #pragma unroll
    for (int mt = 0; mt < 2; mt++) {
        #pragma unroll
        for (int j = 0; j < 8; j++) {
            const int m0 = by * 128 + warp_m * 32 + mt * 16 + gid;
            const int n  = bx * 128 + warp_n * 64 + j * 8 + tig * 2;
            *(float2*)(g_Wh + (size_t) m0      * F_ + n) = make_float2(acc[mt][j][0], acc[mt][j][1]);
            *(float2*)(g_Wh + (size_t)(m0 + 8) * F_ + n) = make_float2(acc[mt][j][2], acc[mt][j][3]);
        }
    }
}

// ---------------------------------------------------------------------------
// Kernel 2: e1[r] = Wh[r,:]·a[:F],  e2[r] = Wh[r,:]·a[F:]    one warp per row
// ---------------------------------------------------------------------------
__global__ void k_rowdots(const float* __restrict__ a) {
    const int gwarp = (blockIdx.x * blockDim.x + threadIdx.x) >> 5;
    const int lane = threadIdx.x & 31;
    if (gwarp >= ROWS) return;
    const float* row = g_Wh + (size_t)gwarp * F_;
    float s1 = 0.f, s2 = 0.f;
    #pragma unroll
    for (int f = lane; f < F_; f += 32) {
        float v = row[f];
        s1 = fmaf(v, a[f], s1);
        s2 = fmaf(v, a[F_ + f], s2);
    }
    #pragma unroll
    for (int o = 16; o; o >>= 1) {
        s1 += __shfl_xor_sync(0xffffffffu, s1, o);
        s2 += __shfl_xor_sync(0xffffffffu, s2, o);
    }
    if (lane == 0) { g_e1[gwarp] = s1; g_e2[gwarp] = s2; }
}

// ---------------------------------------------------------------------------
// Kernel 3: masked leaky-relu + softmax, NO max-subtraction pass.
// Scores are bounded (|e| << 80) so exp can't overflow; masked -> 0.
// Vectorized int4/float4, one block reduction.
// ---------------------------------------------------------------------------
__global__ __launch_bounds__(256) void k_softmax(const int* __restrict__ adj,
                                                 float* __restrict__ att) {
    const int r = blockIdx.x;            // 0 .. ROWS-1
    const int b = r >> 11;               // r / 2048
    __shared__ float s[N_];
    __shared__ float red[8];

    const int4*   arow4 = (const int4*)(adj + (size_t)r * N_);
    const float4* e2b4  = (const float4*)(g_e2 + b * N_);
    const float E1 = g_e1[r];
    const int tid = threadIdx.x, lane = tid & 31, wid = tid >> 5;

    float lsum = 0.f;
    #pragma unroll
    for (int m4 = tid; m4 < N_ / 4; m4 += 256) {   // 2 iterations
        int4   ad = arow4[m4];
        float4 e2 = e2b4[m4];
        float x0 = E1 + e2.x; x0 = x0 > 0.f ? x0 : 0.2f * x0;
        float x1 = E1 + e2.y; x1 = x1 > 0.f ? x1 : 0.2f * x1;
        float x2 = E1 + e2.z; x2 = x2 > 0.f ? x2 : 0.2f * x2;
        float x3 = E1 + e2.w; x3 = x3 > 0.f ? x3 : 0.2f * x3;
        float v0 = ad.x > 0 ? __expf(x0) : 0.f;
        float v1 = ad.y > 0 ? __expf(x1) : 0.f;
        float v2 = ad.z > 0 ? __expf(x2) : 0.f;
        float v3 = ad.w > 0 ? __expf(x3) : 0.f;
        lsum += (v0 + v1) + (v2 + v3);
        ((float4*)s)[m4] = make_float4(v0, v1, v2, v3);
    }
    #pragma unroll
    for (int o = 16; o; o >>= 1) lsum += __shfl_xor_sync(0xffffffffu, lsum, o);
    if (lane == 0) red[wid] = lsum;
    __syncthreads();
    if (tid == 0) {
        float t = 0.f;
        #pragma unroll
        for (int i = 0; i < 8; i++) t += red[i];
        red[0] = 1.0f / t;
    }
    __syncthreads();
    const float inv = red[0];

    float4* orow4 = (float4*)(att + (size_t)r * N_);
    #pragma unroll
    for (int m4 = tid; m4 < N_ / 4; m4 += 256) {
        float4 v = ((float4*)s)[m4];
        orow4[m4] = make_float4(v.x * inv, v.y * inv, v.z * inv, v.w * inv);
    }
}

// ---------------------------------------------------------------------------
// Kernel 4: h_prime = attention @ Wh via tf32 mma, cp.async double-buffered.
//   Per batch: A [2048,2048] @ B [2048,256]. Tile 128x128x32, 2 CTAs/SM.
//   Epilogue: out = h + elu(h_prime).
// ---------------------------------------------------------------------------
__global__ __launch_bounds__(256, 2) void k_gemm_av_mma(const float* __restrict__ att,
                                                        const float* __restrict__ h,
                                                        float* __restrict__ out) {
    extern __shared__ float dsm[];
    const int bz = blockIdx.z;   // batch
    const int bx = blockIdx.x;   // 0..1
    const int by = blockIdx.y;   // 0..15
    const int tid = threadIdx.x;
    const int lane = tid & 31, wid = tid >> 5;
    const int warp_m = wid & 3, warp_n = wid >> 2;
    const int gid = lane >> 2, tig = lane & 3;

    const float* A  = att  + (size_t)bz * N_ * N_ + (size_t)(by * 128) * N_;
    const float* Bg = g_Wh + (size_t)bz * N_ * F_ + bx * 128;

    float acc[2][8][4];
    #pragma unroll
    for (int mt = 0; mt < 2; mt++)
        #pragma unroll
        for (int j = 0; j < 8; j++)
            #pragma unroll
            for (int q = 0; q < 4; q++) acc[mt][j][q] = 0.f;

    // prologue: stage 0
    {
        float* As = dsm + A_OFF;
        float* Bs = dsm + B_OFF;
        #pragma unroll
        for (int i = 0; i < 4; i++) {
            int flat = tid + i * 256, row = flat >> 3, c4 = flat & 7;
            cp16(&As[row * 36 + c4 * 4], A + (size_t)row * N_ + c4 * 4);
        }
        #pragma unroll
        for (int i = 0; i < 4; i++) {
            int flat = tid + i * 256, kr = flat >> 5, c4 = flat & 31;
            cp16(&Bs[kr * 136 + c4 * 4], Bg + (size_t)kr * F_ + c4 * 4);
        }
        cp_commit();
    }

    const int NT = N_ / 32;   // 64
    for (int kt = 0; kt < NT; kt++) {
        const int cur = kt & 1;
        if (kt + 1 < NT) {
            const int k0 = (kt + 1) * 32;
            float* As = dsm + (1 - cur) * STAGE_FLOATS + A_OFF;
            float* Bs = dsm + (1 - cur) * STAGE_FLOATS + B_OFF;
            #pragma unroll
            for (int i = 0; i < 4; i++) {
                int flat = tid + i * 256, row = flat >> 3, c4 = flat & 7;
                cp16(&As[row * 36 + c4 * 4], A + (size_t)row * N_ + k0 + c4 * 4);
            }
            #pragma unroll
            for (int i = 0; i < 4; i++) {
                int flat = tid + i * 256, kr = flat >> 5, c4 = flat & 31;
                cp16(&Bs[kr * 136 + c4 * 4], Bg + (size_t)(k0 + kr) * F_ + c4 * 4);
            }
            cp_commit();
            cp_wait<1>();
        } else {
            cp_wait<0>();
        }
        __syncthreads();

        const float* As = dsm + cur * STAGE_FLOATS + A_OFF;
        const float* Bs = dsm + cur * STAGE_FLOATS + B_OFF;

        #pragma unroll
        for (int kk = 0; kk < 32; kk += 8) {
            uint32_t afr[2][4];
            #pragma unroll
            for (int mt = 0; mt < 2; mt++) {
                int r = warp_m * 32 + mt * 16 + gid;
                afr[mt][0] = __float_as_uint(As[ r      * 36 + kk + tig    ]);
                afr[mt][1] = __float_as_uint(As[(r + 8) * 36 + kk + tig    ]);
                afr[mt][2] = __float_as_uint(As[ r      * 36 + kk + tig + 4]);
                afr[mt][3] = __float_as_uint(As[(r + 8) * 36 + kk + tig + 4]);
            }
            uint32_t bfr[8][2];
            #pragma unroll
            for (int j = 0; j < 8; j++) {
                int n = warp_n * 64 + j * 8 + gid;
                bfr[j][0] = __float_as_uint(Bs[(kk + tig    ) * 136 + n]);
                bfr[j][1] = __float_as_uint(Bs[(kk + tig + 4) * 136 + n]);
            }
            #pragma unroll
            for (int mt = 0; mt < 2; mt++)
                #pragma unroll
                for (int j = 0; j < 8; j++)
                    mma_tf32(acc[mt][j], afr[mt], bfr[j]);
        }
        __syncthreads();
    }

    // epilogue: out = h + elu(h_prime)
    const size_t base = (size_t)bz * N_ * F_;
    #pragma unroll
    for (int mt = 0; mt < 2; mt++) {
        #pragma unroll
        for (int j = 0; j < 8; j++) {
            const int m0 = by * 128 + warp_m * 32 + mt * 16 + gid;
            const int n  = bx * 128 + warp_n * 64 + j * 8 + tig * 2;
            {
                const size_t idx = base + (size_t)m0 * F_ + n;
                float c0 = acc[mt][j][0], c1 = acc[mt][j][1];
                float e0 = c0 > 0.f ? c0 : expm1f(c0);
                float e1 = c1 > 0.f ? c1 : expm1f(c1);
                float2 hv = *(const float2*)(h + idx);
                *(float2*)(out + idx) = make_float2(hv.x + e0, hv.y + e1);
            }
            {
                const size_t idx = base + (size_t)(m0 + 8) * F_ + n;
                float c2 = acc[mt][j][2], c3 = acc[mt][j][3];
                float e2 = c2 > 0.f ? c2 : expm1f(c2);
                float e3 = c3 > 0.f ? c3 : expm1f(c3);
                float2 hv = *(const float2*)(h + idx);
                *(float2*)(out + idx) = make_float2(hv.x + e2, hv.y + e3);
            }
        }
    }
}

// ---------------------------------------------------------------------------
extern "C" void kernel_launch(void* const* d_in, const int* in_sizes, int n_in,
                              void* d_out, int out_size) {
    const float* h   = (const float*)d_in[0];
    const int*   adj = (const int*)  d_in[1];
    const float* W   = (const float*)d_in[2];
    const float* a   = (const float*)d_in[3];
    float* out = (float*)d_out;
    float* att = out + OUT_ELEMS;

    cudaFuncSetAttribute(k_gemm_wh_mma, cudaFuncAttributeMaxDynamicSharedMemorySize, SMEM_BYTES);
    cudaFuncSetAttribute(k_gemm_av_mma, cudaFuncAttributeMaxDynamicSharedMemorySize, SMEM_BYTES);

    // 1. Wh = h @ W  (3xTF32 tensor-core, fp32-accurate)
    k_gemm_wh_mma<<<dim3(2, ROWS / 128), 256, SMEM_BYTES>>>(h, W);
    // 2. e1 / e2 row dots
    k_rowdots<<<ROWS / 8, 256>>>(a);
    // 3. masked softmax -> attention (directly into d_out)
    k_softmax<<<ROWS, 256>>>(adj, att);
    // 4. h_prime = attention @ Wh (tf32 tensor cores) ; out = h + elu(h_prime)
    k_gemm_av_mma<<<dim3(2, N_ / 128, B_), 256, SMEM_BYTES>>>(att, h, out);
}

// round 4
// speedup vs baseline: 5.3043x; 1.1714x over previous
#include <cuda_runtime.h>
#include <cuda_bf16.h>
#include <math.h>
#include <stdint.h>

// Problem constants
#define B_  8
#define N_  2048
#define F_  256
#define ROWS (B_ * N_)            // 16384
#define OUT_ELEMS ((size_t)B_ * N_ * F_)   // 4,194,304

// Scratch (device globals — no allocation allowed)
__device__ float g_Wh[(size_t)B_ * N_ * F_];                 // 16 MB fp32 [b*n][f]
__device__ __nv_bfloat16 g_WhT[(size_t)B_ * F_ * N_];        // 8 MB  bf16 [b][f][n]  (transposed)
__device__ __nv_bfloat16 g_att_bf[(size_t)B_ * N_ * N_];     // 67 MB bf16 [b][n][m]
__device__ __align__(16) float g_e1[ROWS];
__device__ __align__(16) float g_e2[ROWS];

// ---------------------------------------------------------------------------
// MMA / ldmatrix / cp.async helpers
// ---------------------------------------------------------------------------
__device__ __forceinline__ void mma_tf32(float* c, const uint32_t* a, const uint32_t* b) {
    asm volatile(
        "mma.sync.aligned.m16n8k8.row.col.f32.tf32.tf32.f32 "
        "{%0,%1,%2,%3}, {%4,%5,%6,%7}, {%8,%9}, {%0,%1,%2,%3};\n"
        : "+f"(c[0]), "+f"(c[1]), "+f"(c[2]), "+f"(c[3])
        : "r"(a[0]), "r"(a[1]), "r"(a[2]), "r"(a[3]), "r"(b[0]), "r"(b[1]));
}

__device__ __forceinline__ void mma_bf16(float* c, const uint32_t* a, const uint32_t* b) {
    asm volatile(
        "mma.sync.aligned.m16n8k16.row.col.f32.bf16.bf16.f32 "
        "{%0,%1,%2,%3}, {%4,%5,%6,%7}, {%8,%9}, {%0,%1,%2,%3};\n"
        : "+f"(c[0]), "+f"(c[1]), "+f"(c[2]), "+f"(c[3])
        : "r"(a[0]), "r"(a[1]), "r"(a[2]), "r"(a[3]), "r"(b[0]), "r"(b[1]));
}

__device__ __forceinline__ void ldsm_x4(uint32_t& r0, uint32_t& r1, uint32_t& r2, uint32_t& r3,
                                        const void* p) {
    uint32_t a = (uint32_t)__cvta_generic_to_shared(p);
    asm volatile("ldmatrix.sync.aligned.m8n8.x4.shared.b16 {%0,%1,%2,%3}, [%4];"
                 : "=r"(r0), "=r"(r1), "=r"(r2), "=r"(r3) : "r"(a));
}
__device__ __forceinline__ void ldsm_x2(uint32_t& r0, uint32_t& r1, const void* p) {
    uint32_t a = (uint32_t)__cvta_generic_to_shared(p);
    asm volatile("ldmatrix.sync.aligned.m8n8.x2.shared.b16 {%0,%1}, [%2];"
                 : "=r"(r0), "=r"(r1) : "r"(a));
}

__device__ __forceinline__ void split_tf32(float x, uint32_t& hi, uint32_t& lo) {
    uint32_t h_;
    asm("cvt.rna.tf32.f32 %0, %1;" : "=r"(h_) : "f"(x));
    float l = x - __uint_as_float(h_);
    uint32_t l_;
    asm("cvt.rna.tf32.f32 %0, %1;" : "=r"(l_) : "f"(l));
    hi = h_; lo = l_;
}

__device__ __forceinline__ void cp16(void* dst, const void* src) {
    uint32_t d = (uint32_t)__cvta_generic_to_shared(dst);
    asm volatile("cp.async.cg.shared.global [%0], [%1], 16;\n" :: "r"(d), "l"(src));
}
__device__ __forceinline__ void cp_commit() {
    asm volatile("cp.async.commit_group;\n");
}
template<int NPEND> __device__ __forceinline__ void cp_wait() {
    asm volatile("cp.async.wait_group %0;\n" :: "n"(NPEND));
}

// ---------------------------------------------------------------------------
// Kernel 1: Wh = h @ W via 3xTF32 split-precision tensor-core GEMM (accurate).
// ---------------------------------------------------------------------------
#define STAGE_FLOATS 8960           // 4608 (A 128x36) + 4352 (B 32x136)
#define A_OFF 0
#define B_OFF 4608
#define SMEM_BYTES_K1 (2 * STAGE_FLOATS * 4)   // 71680

__global__ __launch_bounds__(256, 2) void k_gemm_wh_mma(const float* __restrict__ h,
                                                        const float* __restrict__ W) {
    extern __shared__ float dsm[];
    const int bx = blockIdx.x;   // 0..1
    const int by = blockIdx.y;   // 0..127
    const int tid = threadIdx.x;
    const int lane = tid & 31, wid = tid >> 5;
    const int warp_m = wid & 3, warp_n = wid >> 2;
    const int gid = lane >> 2, tig = lane & 3;

    const float* A  = h + (size_t)(by * 128) * F_;
    const float* Bg = W + bx * 128;

    float acc[2][8][4];
    #pragma unroll
    for (int mt = 0; mt < 2; mt++)
        #pragma unroll
        for (int j = 0; j < 8; j++)
            #pragma unroll
            for (int q = 0; q < 4; q++) acc[mt][j][q] = 0.f;

    {
        float* As = dsm + A_OFF;
        float* Bs = dsm + B_OFF;
        #pragma unroll
        for (int i = 0; i < 4; i++) {
            int flat = tid + i * 256, row = flat >> 3, c4 = flat & 7;
            cp16(&As[row * 36 + c4 * 4], A + (size_t)row * F_ + c4 * 4);
        }
        #pragma unroll
        for (int i = 0; i < 4; i++) {
            int flat = tid + i * 256, kr = flat >> 5, c4 = flat & 31;
            cp16(&Bs[kr * 136 + c4 * 4], Bg + (size_t)kr * F_ + c4 * 4);
        }
        cp_commit();
    }

    const int NT = F_ / 32;   // 8
    for (int kt = 0; kt < NT; kt++) {
        const int cur = kt & 1;
        if (kt + 1 < NT) {
            const int k0 = (kt + 1) * 32;
            float* As = dsm + (1 - cur) * STAGE_FLOATS + A_OFF;
            float* Bs = dsm + (1 - cur) * STAGE_FLOATS + B_OFF;
            #pragma unroll
            for (int i = 0; i < 4; i++) {
                int flat = tid + i * 256, row = flat >> 3, c4 = flat & 7;
                cp16(&As[row * 36 + c4 * 4], A + (size_t)row * F_ + k0 + c4 * 4);
            }
            #pragma unroll
            for (int i = 0; i < 4; i++) {
                int flat = tid + i * 256, kr = flat >> 5, c4 = flat & 31;
                cp16(&Bs[kr * 136 + c4 * 4], Bg + (size_t)(k0 + kr) * F_ + c4 * 4);
            }
            cp_commit();
            cp_wait<1>();
        } else {
            cp_wait<0>();
        }
        __syncthreads();

        const float* As = dsm + cur * STAGE_FLOATS + A_OFF;
        const float* Bs = dsm + cur * STAGE_FLOATS + B_OFF;

        #pragma unroll
        for (int kk = 0; kk < 32; kk += 8) {
            uint32_t ah[2][4], al[2][4];
            #pragma unroll
            for (int mt = 0; mt < 2; mt++) {
                int r = warp_m * 32 + mt * 16 + gid;
                split_tf32(As[ r      * 36 + kk + tig    ], ah[mt][0], al[mt][0]);
                split_tf32(As[(r + 8) * 36 + kk + tig    ], ah[mt][1], al[mt][1]);
                split_tf32(As[ r      * 36 + kk + tig + 4], ah[mt][2], al[mt][2]);
                split_tf32(As[(r + 8) * 36 + kk + tig + 4], ah[mt][3], al[mt][3]);
            }
            uint32_t bh[8][2], bl[8][2];
            #pragma unroll
            for (int j = 0; j < 8; j++) {
                int n = warp_n * 64 + j * 8 + gid;
                split_tf32(Bs[(kk + tig    ) * 136 + n], bh[j][0], bl[j][0]);
                split_tf32(Bs[(kk + tig + 4) * 136 + n], bh[j][1], bl[j][1]);
            }
            #pragma unroll
            for (int mt = 0; mt < 2; mt++)
                #pragma unroll
                for (int j = 0; j < 8; j++) {
                    mma_tf32(acc[mt][j], ah[mt], bh[j]);
                    mma_tf32(acc[mt][j], al[mt], bh[j]);
                    mma_tf32(acc[mt][j], ah[mt], bl[j]);
                }
        }
        __syncthreads();
    }

    #pragma unroll
    for (int mt = 0; mt < 2; mt++) {
        #pragma unroll
        for (int j = 0; j < 8; j++) {
            const int m0 = by * 128 + warp_m * 32 + mt * 16 + gid;
            const int n  = bx * 128 + warp_n * 64 + j * 8 + tig * 2;
            *(float2*)(g_Wh + (size_t) m0      * F_ + n) = make_float2(acc[mt][j][0], acc[mt][j][1]);
            *(float2*)(g_Wh + (size_t)(m0 + 8) * F_ + n) = make_float2(acc[mt][j][2], acc[mt][j][3]);
        }
    }
}

// ---------------------------------------------------------------------------
// Kernel T: transpose + convert Wh -> g_WhT bf16 [b][f][n]
// ---------------------------------------------------------------------------
__global__ __launch_bounds__(256) void k_transpose_bf() {
    __shared__ float t[32][33];
    const int b  = blockIdx.z;
    const int m0 = blockIdx.x * 32;   // node dim (2048)
    const int n0 = blockIdx.y * 32;   // feature dim (256)
    const int tx = threadIdx.x, ty = threadIdx.y;

    const float* src = g_Wh + ((size_t)b * N_ + m0) * F_ + n0;
    #pragma unroll
    for (int i = 0; i < 4; i++)
        t[ty + i * 8][tx] = src[(size_t)(ty + i * 8) * F_ + tx];
    __syncthreads();

    __nv_bfloat16* dst = g_WhT + ((size_t)b * F_ + n0) * N_ + m0;
    #pragma unroll
    for (int i = 0; i < 4; i++)
        dst[(size_t)(ty + i * 8) * N_ + tx] = __float2bfloat16(t[tx][ty + i * 8]);
}

// ---------------------------------------------------------------------------
// Kernel 2: e1[r] = Wh[r,:]·a[:F],  e2[r] = Wh[r,:]·a[F:]    one warp per row
// ---------------------------------------------------------------------------
__global__ void k_rowdots(const float* __restrict__ a) {
    const int gwarp = (blockIdx.x * blockDim.x + threadIdx.x) >> 5;
    const int lane = threadIdx.x & 31;
    if (gwarp >= ROWS) return;
    const float* row = g_Wh + (size_t)gwarp * F_;
    float s1 = 0.f, s2 = 0.f;
    #pragma unroll
    for (int f = lane; f < F_; f += 32) {
        float v = row[f];
        s1 = fmaf(v, a[f], s1);
        s2 = fmaf(v, a[F_ + f], s2);
    }
    #pragma unroll
    for (int o = 16; o; o >>= 1) {
        s1 += __shfl_xor_sync(0xffffffffu, s1, o);
        s2 += __shfl_xor_sync(0xffffffffu, s2, o);
    }
    if (lane == 0) { g_e1[gwarp] = s1; g_e2[gwarp] = s2; }
}

// ---------------------------------------------------------------------------
// Kernel 3: masked leaky-relu + softmax (no max pass; scores bounded).
// Writes fp32 attention to d_out AND bf16 copy to g_att_bf.
// ---------------------------------------------------------------------------
__global__ __launch_bounds__(256) void k_softmax(const int* __restrict__ adj,
                                                 float* __restrict__ att) {
    const int r = blockIdx.x;            // 0 .. ROWS-1
    const int b = r >> 11;
    __shared__ float s[N_];
    __shared__ float red[8];

    const int4*   arow4 = (const int4*)(adj + (size_t)r * N_);
    const float4* e2b4  = (const float4*)(g_e2 + b * N_);
    const float E1 = g_e1[r];
    const int tid = threadIdx.x, lane = tid & 31, wid = tid >> 5;

    float lsum = 0.f;
    #pragma unroll
    for (int m4 = tid; m4 < N_ / 4; m4 += 256) {
        int4   ad = arow4[m4];
        float4 e2 = e2b4[m4];
        float x0 = E1 + e2.x; x0 = x0 > 0.f ? x0 : 0.2f * x0;
        float x1 = E1 + e2.y; x1 = x1 > 0.f ? x1 : 0.2f * x1;
        float x2 = E1 + e2.z; x2 = x2 > 0.f ? x2 : 0.2f * x2;
        float x3 = E1 + e2.w; x3 = x3 > 0.f ? x3 : 0.2f * x3;
        float v0 = ad.x > 0 ? __expf(x0) : 0.f;
        float v1 = ad.y > 0 ? __expf(x1) : 0.f;
        float v2 = ad.z > 0 ? __expf(x2) : 0.f;
        float v3 = ad.w > 0 ? __expf(x3) : 0.f;
        lsum += (v0 + v1) + (v2 + v3);
        ((float4*)s)[m4] = make_float4(v0, v1, v2, v3);
    }
    #pragma unroll
    for (int o = 16; o; o >>= 1) lsum += __shfl_xor_sync(0xffffffffu, lsum, o);
    if (lane == 0) red[wid] = lsum;
    __syncthreads();
    if (tid == 0) {
        float t = 0.f;
        #pragma unroll
        for (int i = 0; i < 8; i++) t += red[i];
        red[0] = 1.0f / t;
    }
    __syncthreads();
    const float inv = red[0];

    float4* orow4 = (float4*)(att + (size_t)r * N_);
    __nv_bfloat162* brow2 = (__nv_bfloat162*)(g_att_bf + (size_t)r * N_);
    #pragma unroll
    for (int m4 = tid; m4 < N_ / 4; m4 += 256) {
        float4 v = ((float4*)s)[m4];
        float4 o = make_float4(v.x * inv, v.y * inv, v.z * inv, v.w * inv);
        orow4[m4] = o;
        brow2[m4 * 2    ] = __floats2bfloat162_rn(o.x, o.y);
        brow2[m4 * 2 + 1] = __floats2bfloat162_rn(o.z, o.w);
    }
}

// ---------------------------------------------------------------------------
// Kernel 4: h_prime = attention @ Wh in bf16 m16n8k16 + ldmatrix.
//   A = g_att_bf [m][k] bf16, B = g_WhT [n][k] bf16. Tile 128x128x32.
//   Epilogue: out = h + elu(h_prime).
// ---------------------------------------------------------------------------
#define HSTRIDE 40                 // bf16 elems per smem row (80 B): ldmatrix conflict-free
#define STAGE_H (2 * 128 * HSTRIDE)  // A + B per stage, bf16 elems (10240)
#define SMEM_BYTES_K4 (2 * STAGE_H * 2)  // 40960 B

__global__ __launch_bounds__(256, 2) void k_gemm_av_bf16(const float* __restrict__ h,
                                                         float* __restrict__ out) {
    extern __shared__ __nv_bfloat16 hsm[];
    const int bz = blockIdx.z;
    const int bx = blockIdx.x;   // 0..1 (n tile of 128)
    const int by = blockIdx.y;   // 0..15 (m tile of 128)
    const int tid = threadIdx.x;
    const int lane = tid & 31, wid = tid >> 5;
    const int warp_m = wid & 3, warp_n = wid >> 2;
    const int gid = lane >> 2, tig = lane & 3;

    const __nv_bfloat16* A  = g_att_bf + (size_t)bz * N_ * N_ + (size_t)(by * 128) * N_;
    const __nv_bfloat16* Bt = g_WhT   + (size_t)bz * F_ * N_ + (size_t)(bx * 128) * N_;

    float acc[2][8][4];
    #pragma unroll
    for (int mt = 0; mt < 2; mt++)
        #pragma unroll
        for (int j = 0; j < 8; j++)
            #pragma unroll
            for (int q = 0; q < 4; q++) acc[mt][j][q] = 0.f;

    // stage layout: As = 128 rows x HSTRIDE (k), Bs = 128 n-rows x HSTRIDE (k)
    // copy: 128 rows x 4 chunks of 16B (8 bf16) each = 512 cp16 per matrix
    {
        __nv_bfloat16* As = hsm;
        __nv_bfloat16* Bs = hsm + 128 * HSTRIDE;
        #pragma unroll
        for (int i = 0; i < 2; i++) {
            int flat = tid + i * 256, row = flat >> 2, c = flat & 3;
            cp16(&As[row * HSTRIDE + c * 8], A + (size_t)row * N_ + c * 8);
        }
        #pragma unroll
        for (int i = 0; i < 2; i++) {
            int flat = tid + i * 256, row = flat >> 2, c = flat & 3;
            cp16(&Bs[row * HSTRIDE + c * 8], Bt + (size_t)row * N_ + c * 8);
        }
        cp_commit();
    }

    // per-lane ldmatrix source row/col offsets
    const int a_mat = lane >> 3, a_r = lane & 7;
    const int a_row_off = ((a_mat & 1) << 3) + a_r;     // + mt*16 + warp_m*32
    const int a_k_off   = (a_mat >> 1) << 3;            // + kk
    const int b_mat = (lane >> 3) & 1, b_r = lane & 7;
    const int b_row_off = b_r;                          // + j*8 + warp_n*64
    const int b_k_off   = b_mat << 3;                   // + kk

    const int NT = N_ / 32;   // 64
    for (int kt = 0; kt < NT; kt++) {
        const int cur = kt & 1;
        if (kt + 1 < NT) {
            const int k0 = (kt + 1) * 32;
            __nv_bfloat16* As = hsm + (1 - cur) * STAGE_H;
            __nv_bfloat16* Bs = As + 128 * HSTRIDE;
            #pragma unroll
            for (int i = 0; i < 2; i++) {
                int flat = tid + i * 256, row = flat >> 2, c = flat & 3;
                cp16(&As[row * HSTRIDE + c * 8], A + (size_t)row * N_ + k0 + c * 8);
            }
            #pragma unroll
            for (int i = 0; i < 2; i++) {
                int flat = tid + i * 256, row = flat >> 2, c = flat & 3;
                cp16(&Bs[row * HSTRIDE + c * 8], Bt + (size_t)row * N_ + k0 + c * 8);
            }
            cp_commit();
            cp_wait<1>();
        } else {
            cp_wait<0>();
        }
        __syncthreads();

        const __nv_bfloat16* As = hsm + cur * STAGE_H;
        const __nv_bfloat16* Bs = As + 128 * HSTRIDE;

        #pragma unroll
        for (int kk = 0; kk < 32; kk += 16) {
            uint32_t af[2][4];
            #pragma unroll
            for (int mt = 0; mt < 2; mt++) {
                const __nv_bfloat16* p =
                    As + (warp_m * 32 + mt * 16 + a_row_off) * HSTRIDE + kk + a_k_off;
                ldsm_x4(af[mt][0], af[mt][1], af[mt][2], af[mt][3], p);
            }
            uint32_t bf[8][2];
            #pragma unroll
            for (int j = 0; j < 8; j++) {
                const __nv_bfloat16* p =
                    Bs + (warp_n * 64 + j * 8 + b_row_off) * HSTRIDE + kk + b_k_off;
                ldsm_x2(bf[j][0], bf[j][1], p);
            }
            #pragma unroll
            for (int mt = 0; mt < 2; mt++)
                #pragma unroll
                for (int j = 0; j < 8; j++)
                    mma_bf16(acc[mt][j], af[mt], bf[j]);
        }
        __syncthreads();
    }

    // epilogue: out = h + elu(h_prime)
    const size_t base = (size_t)bz * N_ * F_;
    #pragma unroll
    for (int mt = 0; mt < 2; mt++) {
        #pragma unroll
        for (int j = 0; j < 8; j++) {
            const int m0 = by * 128 + warp_m * 32 + mt * 16 + gid;
            const int n  = bx * 128 + warp_n * 64 + j * 8 + tig * 2;
            {
                const size_t idx = base + (size_t)m0 * F_ + n;
                float c0 = acc[mt][j][0], c1 = acc[mt][j][1];
                float e0 = c0 > 0.f ? c0 : expm1f(c0);
                float e1 = c1 > 0.f ? c1 : expm1f(c1);
                float2 hv = *(const float2*)(h + idx);
                *(float2*)(out + idx) = make_float2(hv.x + e0, hv.y + e1);
            }
            {
                const size_t idx = base + (size_t)(m0 + 8) * F_ + n;
                float c2 = acc[mt][j][2], c3 = acc[mt][j][3];
                float e2 = c2 > 0.f ? c2 : expm1f(c2);
                float e3 = c3 > 0.f ? c3 : expm1f(c3);
                float2 hv = *(const float2*)(h + idx);
                *(float2*)(out + idx) = make_float2(hv.x + e2, hv.y + e3);
            }
        }
    }
}

// ---------------------------------------------------------------------------
extern "C" void kernel_launch(void* const* d_in, const int* in_sizes, int n_in,
                              void* d_out, int out_size) {
    const float* h   = (const float*)d_in[0];
    const int*   adj = (const int*)  d_in[1];
    const float* W   = (const float*)d_in[2];
    const float* a   = (const float*)d_in[3];
    float* out = (float*)d_out;
    float* att = out + OUT_ELEMS;

    cudaFuncSetAttribute(k_gemm_wh_mma,  cudaFuncAttributeMaxDynamicSharedMemorySize, SMEM_BYTES_K1);
    cudaFuncSetAttribute(k_gemm_av_bf16, cudaFuncAttributeMaxDynamicSharedMemorySize, SMEM_BYTES_K4);

    // 1. Wh = h @ W  (3xTF32 tensor-core, fp32-accurate)
    k_gemm_wh_mma<<<dim3(2, ROWS / 128), 256, SMEM_BYTES_K1>>>(h, W);
    // T. Wh -> bf16 transposed copy for k4 B operand
    k_transpose_bf<<<dim3(N_ / 32, F_ / 32, B_), dim3(32, 8)>>>();
    // 2. e1 / e2 row dots
    k_rowdots<<<ROWS / 8, 256>>>(a);
    // 3. masked softmax -> attention fp32 (d_out) + bf16 scratch
    k_softmax<<<ROWS, 256>>>(adj, att);
    // 4. h_prime = attention @ Wh (bf16 tensor cores) ; out = h + elu(h_prime)
    k_gemm_av_bf16<<<dim3(2, N_ / 128, B_), 256, SMEM_BYTES_K4>>>(h, out);
}

// round 6
// speedup vs baseline: 6.3622x; 1.1994x over previous
#include <cuda_runtime.h>
#include <cuda_bf16.h>
#include <math.h>
#include <stdint.h>

// Problem constants
#define B_  8
#define N_  2048
#define F_  256
#define ROWS (B_ * N_)            // 16384
#define OUT_ELEMS ((size_t)B_ * N_ * F_)   // 4,194,304

// Scratch (device globals — no allocation allowed)
__device__ __nv_bfloat16 g_Whb[(size_t)B_ * N_ * F_];        // 8 MB bf16 [b][node m][feat f]
__device__ __nv_bfloat16 g_att_bf[(size_t)B_ * N_ * N_];     // 67 MB bf16 [b][n][m]
__device__ __align__(16) float g_e1[ROWS];
__device__ __align__(16) float g_e2[ROWS];
__device__ __align__(16) float g_w1[F_];
__device__ __align__(16) float g_w2[F_];

// ---------------------------------------------------------------------------
// MMA / ldmatrix / cp.async helpers
// ---------------------------------------------------------------------------
__device__ __forceinline__ void mma_tf32(float* c, const uint32_t* a, const uint32_t* b) {
    asm volatile(
        "mma.sync.aligned.m16n8k8.row.col.f32.tf32.tf32.f32 "
        "{%0,%1,%2,%3}, {%4,%5,%6,%7}, {%8,%9}, {%0,%1,%2,%3};\n"
        : "+f"(c[0]), "+f"(c[1]), "+f"(c[2]), "+f"(c[3])
        : "r"(a[0]), "r"(a[1]), "r"(a[2]), "r"(a[3]), "r"(b[0]), "r"(b[1]));
}

__device__ __forceinline__ void mma_bf16(float* c, const uint32_t* a, const uint32_t* b) {
    asm volatile(
        "mma.sync.aligned.m16n8k16.row.col.f32.bf16.bf16.f32 "
        "{%0,%1,%2,%3}, {%4,%5,%6,%7}, {%8,%9}, {%0,%1,%2,%3};\n"
        : "+f"(c[0]), "+f"(c[1]), "+f"(c[2]), "+f"(c[3])
        : "r"(a[0]), "r"(a[1]), "r"(a[2]), "r"(a[3]), "r"(b[0]), "r"(b[1]));
}

__device__ __forceinline__ void ldsm_x4(uint32_t& r0, uint32_t& r1, uint32_t& r2, uint32_t& r3,
                                        const void* p) {
    uint32_t a = (uint32_t)__cvta_generic_to_shared(p);
    asm volatile("ldmatrix.sync.aligned.m8n8.x4.shared.b16 {%0,%1,%2,%3}, [%4];"
                 : "=r"(r0), "=r"(r1), "=r"(r2), "=r"(r3) : "r"(a));
}
__device__ __forceinline__ void ldsm_x2_t(uint32_t& r0, uint32_t& r1, const void* p) {
    uint32_t a = (uint32_t)__cvta_generic_to_shared(p);
    asm volatile("ldmatrix.sync.aligned.m8n8.x2.trans.shared.b16 {%0,%1}, [%2];"
                 : "=r"(r0), "=r"(r1) : "r"(a));
}

__device__ __forceinline__ void cp16(void* dst, const void* src) {
    uint32_t d = (uint32_t)__cvta_generic_to_shared(dst);
    asm volatile("cp.async.cg.shared.global [%0], [%1], 16;\n" :: "r"(d), "l"(src));
}
__device__ __forceinline__ void cp_commit() {
    asm volatile("cp.async.commit_group;\n");
}
template<int NPEND> __device__ __forceinline__ void cp_wait() {
    asm volatile("cp.async.wait_group %0;\n" :: "n"(NPEND));
}

// ---------------------------------------------------------------------------
// Kernel 0: w1[r] = W[r,:]·a[:F],  w2[r] = W[r,:]·a[F:]   (W @ a, ROW dots)
// One warp per row, coalesced.  (Round-5 bug: this was computed as W^T @ a.)
// ---------------------------------------------------------------------------
__global__ void k_wa(const float* __restrict__ W, const float* __restrict__ a) {
    const int r = (blockIdx.x * blockDim.x + threadIdx.x) >> 5;   // 0..255
    const int lane = threadIdx.x & 31;
    if (r >= F_) return;
    const float* row = W + (size_t)r * F_;
    float s1 = 0.f, s2 = 0.f;
    #pragma unroll
    for (int f = lane; f < F_; f += 32) {
        float w = row[f];
        s1 = fmaf(w, a[f],      s1);
        s2 = fmaf(w, a[F_ + f], s2);
    }
    #pragma unroll
    for (int o = 16; o; o >>= 1) {
        s1 += __shfl_xor_sync(0xffffffffu, s1, o);
        s2 += __shfl_xor_sync(0xffffffffu, s2, o);
    }
    if (lane == 0) { g_w1[r] = s1; g_w2[r] = s2; }
}

// ---------------------------------------------------------------------------
// Kernel E: e1[r] = h[r,:]·w1, e2[r] = h[r,:]·w2   (one warp per row, exact)
// ---------------------------------------------------------------------------
__global__ void k_rowdots(const float* __restrict__ h) {
    const int gwarp = (blockIdx.x * blockDim.x + threadIdx.x) >> 5;
    const int lane = threadIdx.x & 31;
    if (gwarp >= ROWS) return;
    const float4* row = (const float4*)(h + (size_t)gwarp * F_);
    const float4* w1v = (const float4*)g_w1;
    const float4* w2v = (const float4*)g_w2;
    float s1 = 0.f, s2 = 0.f;
    #pragma unroll
    for (int f4 = lane; f4 < F_ / 4; f4 += 32) {   // 2 iterations
        float4 v = row[f4], w1 = w1v[f4], w2 = w2v[f4];
        s1 = fmaf(v.x, w1.x, fmaf(v.y, w1.y, fmaf(v.z, w1.z, fmaf(v.w, w1.w, s1))));
        s2 = fmaf(v.x, w2.x, fmaf(v.y, w2.y, fmaf(v.z, w2.z, fmaf(v.w, w2.w, s2))));
    }
    #pragma unroll
    for (int o = 16; o; o >>= 1) {
        s1 += __shfl_xor_sync(0xffffffffu, s1, o);
        s2 += __shfl_xor_sync(0xffffffffu, s2, o);
    }
    if (lane == 0) { g_e1[gwarp] = s1; g_e2[gwarp] = s2; }
}

// ---------------------------------------------------------------------------
// Kernel 1: Whb(bf16) = h @ W via single-pass TF32 MMA (tile 128x128x32).
// Accuracy only needs to serve the h_prime bf16 path.
// ---------------------------------------------------------------------------
#define STAGE_FLOATS 8960           // 4608 (A 128x36) + 4352 (B 32x136)
#define A_OFF 0
#define B_OFF 4608
#define SMEM_BYTES_K1 (2 * STAGE_FLOATS * 4)   // 71680

__global__ __launch_bounds__(256, 2) void k_gemm_wh(const float* __restrict__ h,
                                                    const float* __restrict__ W) {
    extern __shared__ float dsm[];
    const int bx = blockIdx.x;   // 0..1
    const int by = blockIdx.y;   // 0..127
    const int tid = threadIdx.x;
    const int lane = tid & 31, wid = tid >> 5;
    const int warp_m = wid & 3, warp_n = wid >> 2;
    const int gid = lane >> 2, tig = lane & 3;

    const float* A  = h + (size_t)(by * 128) * F_;
    const float* Bg = W + bx * 128;

    float acc[2][8][4];
    #pragma unroll
    for (int mt = 0; mt < 2; mt++)
        #pragma unroll
        for (int j = 0; j < 8; j++)
            #pragma unroll
            for (int q = 0; q < 4; q++) acc[mt][j][q] = 0.f;

    {
        float* As = dsm + A_OFF;
        float* Bs = dsm + B_OFF;
        #pragma unroll
        for (int i = 0; i < 4; i++) {
            int flat = tid + i * 256, row = flat >> 3, c4 = flat & 7;
            cp16(&As[row * 36 + c4 * 4], A + (size_t)row * F_ + c4 * 4);
        }
        #pragma unroll
        for (int i = 0; i < 4; i++) {
            int flat = tid + i * 256, kr = flat >> 5, c4 = flat & 31;
            cp16(&Bs[kr * 136 + c4 * 4], Bg + (size_t)kr * F_ + c4 * 4);
        }
        cp_commit();
    }

    const int NT = F_ / 32;   // 8
    for (int kt = 0; kt < NT; kt++) {
        const int cur = kt & 1;
        if (kt + 1 < NT) {
            const int k0 = (kt + 1) * 32;
            float* As = dsm + (1 - cur) * STAGE_FLOATS + A_OFF;
            float* Bs = dsm + (1 - cur) * STAGE_FLOATS + B_OFF;
            #pragma unroll
            for (int i = 0; i < 4; i++) {
                int flat = tid + i * 256, row = flat >> 3, c4 = flat & 7;
                cp16(&As[row * 36 + c4 * 4], A + (size_t)row * F_ + k0 + c4 * 4);
            }
            #pragma unroll
            for (int i = 0; i < 4; i++) {
                int flat = tid + i * 256, kr = flat >> 5, c4 = flat & 31;
                cp16(&Bs[kr * 136 + c4 * 4], Bg + (size_t)(k0 + kr) * F_ + c4 * 4);
            }
            cp_commit();
            cp_wait<1>();
        } else {
            cp_wait<0>();
        }
        __syncthreads();

        const float* As = dsm + cur * STAGE_FLOATS + A_OFF;
        const float* Bs = dsm + cur * STAGE_FLOATS + B_OFF;

        #pragma unroll
        for (int kk = 0; kk < 32; kk += 8) {
            uint32_t afr[2][4];
            #pragma unroll
            for (int mt = 0; mt < 2; mt++) {
                int r = warp_m * 32 + mt * 16 + gid;
                afr[mt][0] = __float_as_uint(As[ r      * 36 + kk + tig    ]);
                afr[mt][1] = __float_as_uint(As[(r + 8) * 36 + kk + tig    ]);
                afr[mt][2] = __float_as_uint(As[ r      * 36 + kk + tig + 4]);
                afr[mt][3] = __float_as_uint(As[(r + 8) * 36 + kk + tig + 4]);
            }
            uint32_t bfr[8][2];
            #pragma unroll
            for (int j = 0; j < 8; j++) {
                int n = warp_n * 64 + j * 8 + gid;
                bfr[j][0] = __float_as_uint(Bs[(kk + tig    ) * 136 + n]);
                bfr[j][1] = __float_as_uint(Bs[(kk + tig + 4) * 136 + n]);
            }
            #pragma unroll
            for (int mt = 0; mt < 2; mt++)
                #pragma unroll
                for (int j = 0; j < 8; j++)
                    mma_tf32(acc[mt][j], afr[mt], bfr[j]);
        }
        __syncthreads();
    }

    // epilogue: bf16 store, natural [m][f] layout
    #pragma unroll
    for (int mt = 0; mt < 2; mt++) {
        #pragma unroll
        for (int j = 0; j < 8; j++) {
            const int m0 = by * 128 + warp_m * 32 + mt * 16 + gid;
            const int n  = bx * 128 + warp_n * 64 + j * 8 + tig * 2;
            *(__nv_bfloat162*)(g_Whb + (size_t) m0      * F_ + n) =
                __floats2bfloat162_rn(acc[mt][j][0], acc[mt][j][1]);
            *(__nv_bfloat162*)(g_Whb + (size_t)(m0 + 8) * F_ + n) =
                __floats2bfloat162_rn(acc[mt][j][2], acc[mt][j][3]);
        }
    }
}

// ---------------------------------------------------------------------------
// Kernel 3: masked leaky-relu + softmax (no max pass; scores bounded).
// Writes fp32 attention to d_out AND bf16 copy to g_att_bf.
// ---------------------------------------------------------------------------
__global__ __launch_bounds__(256) void k_softmax(const int* __restrict__ adj,
                                                 float* __restrict__ att) {
    const int r = blockIdx.x;            // 0 .. ROWS-1
    const int b = r >> 11;
    __shared__ float s[N_];
    __shared__ float red[8];

    const int4*   arow4 = (const int4*)(adj + (size_t)r * N_);
    const float4* e2b4  = (const float4*)(g_e2 + b * N_);
    const float E1 = g_e1[r];
    const int tid = threadIdx.x, lane = tid & 31, wid = tid >> 5;

    float lsum = 0.f;
    #pragma unroll
    for (int m4 = tid; m4 < N_ / 4; m4 += 256) {
        int4   ad = arow4[m4];
        float4 e2 = e2b4[m4];
        float x0 = E1 + e2.x; x0 = x0 > 0.f ? x0 : 0.2f * x0;
        float x1 = E1 + e2.y; x1 = x1 > 0.f ? x1 : 0.2f * x1;
        float x2 = E1 + e2.z; x2 = x2 > 0.f ? x2 : 0.2f * x2;
        float x3 = E1 + e2.w; x3 = x3 > 0.f ? x3 : 0.2f * x3;
        float v0 = ad.x > 0 ? __expf(x0) : 0.f;
        float v1 = ad.y > 0 ? __expf(x1) : 0.f;
        float v2 = ad.z > 0 ? __expf(x2) : 0.f;
        float v3 = ad.w > 0 ? __expf(x3) : 0.f;
        lsum += (v0 + v1) + (v2 + v3);
        ((float4*)s)[m4] = make_float4(v0, v1, v2, v3);
    }
    #pragma unroll
    for (int o = 16; o; o >>= 1) lsum += __shfl_xor_sync(0xffffffffu, lsum, o);
    if (lane == 0) red[wid] = lsum;
    __syncthreads();
    if (tid == 0) {
        float t = 0.f;
        #pragma unroll
        for (int i = 0; i < 8; i++) t += red[i];
        red[0] = 1.0f / t;
    }
    __syncthreads();
    const float inv = red[0];

    float4* orow4 = (float4*)(att + (size_t)r * N_);
    __nv_bfloat162* brow2 = (__nv_bfloat162*)(g_att_bf + (size_t)r * N_);
    #pragma unroll
    for (int m4 = tid; m4 < N_ / 4; m4 += 256) {
        float4 v = ((float4*)s)[m4];
        float4 o = make_float4(v.x * inv, v.y * inv, v.z * inv, v.w * inv);
        orow4[m4] = o;
        brow2[m4 * 2    ] = __floats2bfloat162_rn(o.x, o.y);
        brow2[m4 * 2 + 1] = __floats2bfloat162_rn(o.z, o.w);
    }
}

// ---------------------------------------------------------------------------
// Kernel 4: h_prime = attention @ Wh, bf16 m16n8k16.
//   A = g_att_bf [m][k] (ldmatrix),  B = g_Whb [k][n] (ldmatrix.trans).
//   Tile 128x128x32.  Epilogue: out = h + elu(h_prime).
// ---------------------------------------------------------------------------
#define HSTRIDE 40                        // A smem row: 32 bf16 + 8 pad (80 B)
#define BSTRIDE_H 136                     // B smem row: 128 bf16 + 8 pad (272 B)
#define A_ELEMS (128 * HSTRIDE)           // 5120
#define STAGE_H (A_ELEMS + 32 * BSTRIDE_H)   // 5120 + 4352 = 9472 bf16
#define SMEM_BYTES_K4 (2 * STAGE_H * 2)   // 37888 B

__global__ __launch_bounds__(256, 2) void k_gemm_av_bf16(const float* __restrict__ h,
                                                         float* __restrict__ out) {
    extern __shared__ __nv_bfloat16 hsm[];
    const int bz = blockIdx.z;
    const int bx = blockIdx.x;   // 0..1 (n tile of 128)
    const int by = blockIdx.y;   // 0..15 (m tile of 128)
    const int tid = threadIdx.x;
    const int lane = tid & 31, wid = tid >> 5;
    const int warp_m = wid & 3, warp_n = wid >> 2;
    const int gid = lane >> 2, tig = lane & 3;

    const __nv_bfloat16* A  = g_att_bf + (size_t)bz * N_ * N_ + (size_t)(by * 128) * N_;
    const __nv_bfloat16* Bw = g_Whb   + (size_t)bz * N_ * F_ + bx * 128;

    float acc[2][8][4];
    #pragma unroll
    for (int mt = 0; mt < 2; mt++)
        #pragma unroll
        for (int j = 0; j < 8; j++)
            #pragma unroll
            for (int q = 0; q < 4; q++) acc[mt][j][q] = 0.f;

    // stage: As = 128 m-rows x 32 k  |  Bs = 32 k-rows x 128 n
    {
        __nv_bfloat16* As = hsm;
        __nv_bfloat16* Bs = hsm + A_ELEMS;
        #pragma unroll
        for (int i = 0; i < 2; i++) {
            int flat = tid + i * 256, row = flat >> 2, c = flat & 3;
            cp16(&As[row * HSTRIDE + c * 8], A + (size_t)row * N_ + c * 8);
        }
        #pragma unroll
        for (int i = 0; i < 2; i++) {
            int flat = tid + i * 256, kr = flat >> 4, c = flat & 15;
            cp16(&Bs[kr * BSTRIDE_H + c * 8], Bw + (size_t)kr * F_ + c * 8);
        }
        cp_commit();
    }

    // ldmatrix lane offsets
    const int a_mat = lane >> 3, a_r = lane & 7;
    const int a_row_off = ((a_mat & 1) << 3) + a_r;     // + mt*16 + warp_m*32
    const int a_k_off   = (a_mat >> 1) << 3;            // + kk
    const int b_k_lane  = lane & 15;                    // rows kk..kk+15 (x2.trans)

    const int NT = N_ / 32;   // 64
    for (int kt = 0; kt < NT; kt++) {
        const int cur = kt & 1;
        if (kt + 1 < NT) {
            const int k0 = (kt + 1) * 32;
            __nv_bfloat16* As = hsm + (1 - cur) * STAGE_H;
            __nv_bfloat16* Bs = As + A_ELEMS;
            #pragma unroll
            for (int i = 0; i < 2; i++) {
                int flat = tid + i * 256, row = flat >> 2, c = flat & 3;
                cp16(&As[row * HSTRIDE + c * 8], A + (size_t)row * N_ + k0 + c * 8);
            }
            #pragma unroll
            for (int i = 0; i < 2; i++) {
                int flat = tid + i * 256, kr = flat >> 4, c = flat & 15;
                cp16(&Bs[kr * BSTRIDE_H + c * 8], Bw + (size_t)(k0 + kr) * F_ + c * 8);
            }
            cp_commit();
            cp_wait<1>();
        } else {
            cp_wait<0>();
        }
        __syncthreads();

        const __nv_bfloat16* As = hsm + cur * STAGE_H;
        const __nv_bfloat16* Bs = As + A_ELEMS;

        #pragma unroll
        for (int kk = 0; kk < 32; kk += 16) {
            uint32_t af[2][4];
            #pragma unroll
            for (int mt = 0; mt < 2; mt++) {
                const __nv_bfloat16* p =
                    As + (warp_m * 32 + mt * 16 + a_row_off) * HSTRIDE + kk + a_k_off;
                ldsm_x4(af[mt][0], af[mt][1], af[mt][2], af[mt][3], p);
            }
            uint32_t bf[8][2];
            #pragma unroll
            for (int j = 0; j < 8; j++) {
                const __nv_bfloat16* p =
                    Bs + (kk + b_k_lane) * BSTRIDE_H + warp_n * 64 + j * 8;
                ldsm_x2_t(bf[j][0], bf[j][1], p);
            }
            #pragma unroll
            for (int mt = 0; mt < 2; mt++)
                #pragma unroll
                for (int j = 0; j < 8; j++)
                    mma_bf16(acc[mt][j], af[mt], bf[j]);
        }
        __syncthreads();
    }

    // epilogue: out = h + elu(h_prime)
    const size_t base = (size_t)bz * N_ * F_;
    #pragma unroll
    for (int mt = 0; mt < 2; mt++) {
        #pragma unroll
        for (int j = 0; j < 8; j++) {
            const int m0 = by * 128 + warp_m * 32 + mt * 16 + gid;
            const int n  = bx * 128 + warp_n * 64 + j * 8 + tig * 2;
            {
                const size_t idx = base + (size_t)m0 * F_ + n;
                float c0 = acc[mt][j][0], c1 = acc[mt][j][1];
                float e0 = c0 > 0.f ? c0 : expm1f(c0);
                float e1 = c1 > 0.f ? c1 : expm1f(c1);
                float2 hv = *(const float2*)(h + idx);
                *(float2*)(out + idx) = make_float2(hv.x + e0, hv.y + e1);
            }
            {
                const size_t idx = base + (size_t)(m0 + 8) * F_ + n;
                float c2 = acc[mt][j][2], c3 = acc[mt][j][3];
                float e2 = c2 > 0.f ? c2 : expm1f(c2);
                float e3 = c3 > 0.f ? c3 : expm1f(c3);
                float2 hv = *(const float2*)(h + idx);
                *(float2*)(out + idx) = make_float2(hv.x + e2, hv.y + e3);
            }
        }
    }
}

// ---------------------------------------------------------------------------
extern "C" void kernel_launch(void* const* d_in, const int* in_sizes, int n_in,
                              void* d_out, int out_size) {
    const float* h   = (const float*)d_in[0];
    const int*   adj = (const int*)  d_in[1];
    const float* W   = (const float*)d_in[2];
    const float* a   = (const float*)d_in[3];
    float* out = (float*)d_out;
    float* att = out + OUT_ELEMS;

    cudaFuncSetAttribute(k_gemm_wh,      cudaFuncAttributeMaxDynamicSharedMemorySize, SMEM_BYTES_K1);
    cudaFuncSetAttribute(k_gemm_av_bf16, cudaFuncAttributeMaxDynamicSharedMemorySize, SMEM_BYTES_K4);

    // 0. w1/w2 = W @ a  (row dots; exact)
    k_wa<<<F_ / 8, 256>>>(W, a);
    // E. e1/e2 = h @ w1/w2  (exact fp32 scores)
    k_rowdots<<<ROWS / 8, 256>>>(h);
    // 1. Whb(bf16) = h @ W  (single-pass tf32)
    k_gemm_wh<<<dim3(2, ROWS / 128), 256, SMEM_BYTES_K1>>>(h, W);
    // 3. masked softmax -> attention fp32 (d_out) + bf16 scratch
    k_softmax<<<ROWS, 256>>>(adj, att);
    // 4. h_prime = attention @ Wh (bf16 tensor cores) ; out = h + elu(h_prime)
    k_gemm_av_bf16<<<dim3(2, N_ / 128, B_), 256, SMEM_BYTES_K4>>>(h, out);
}

// round 8
// speedup vs baseline: 6.6236x; 1.0411x over previous
#include <cuda_runtime.h>
#include <cuda_bf16.h>
#include <math.h>
#include <stdint.h>

// Problem constants
#define B_  8
#define N_  2048
#define F_  256
#define ROWS (B_ * N_)            // 16384
#define OUT_ELEMS ((size_t)B_ * N_ * F_)   // 4,194,304

// Scratch (device globals — no allocation allowed)
__device__ __nv_bfloat16 g_Whb[(size_t)B_ * N_ * F_];        // 8 MB bf16 [b][node m][feat f]
__device__ __nv_bfloat16 g_att_bf[(size_t)B_ * N_ * N_];     // 67 MB bf16 [b][n][m]
__device__ __align__(16) float g_e1[ROWS];
__device__ __align__(16) float g_e2[ROWS];
__device__ __align__(16) float g_w1[F_];
__device__ __align__(16) float g_w2[F_];

// ---------------------------------------------------------------------------
// MMA / ldmatrix / cp.async helpers
// ---------------------------------------------------------------------------
__device__ __forceinline__ void mma_tf32(float* c, const uint32_t* a, const uint32_t* b) {
    asm volatile(
        "mma.sync.aligned.m16n8k8.row.col.f32.tf32.tf32.f32 "
        "{%0,%1,%2,%3}, {%4,%5,%6,%7}, {%8,%9}, {%0,%1,%2,%3};\n"
        : "+f"(c[0]), "+f"(c[1]), "+f"(c[2]), "+f"(c[3])
        : "r"(a[0]), "r"(a[1]), "r"(a[2]), "r"(a[3]), "r"(b[0]), "r"(b[1]));
}

__device__ __forceinline__ void mma_bf16(float* c, const uint32_t* a, const uint32_t* b) {
    asm volatile(
        "mma.sync.aligned.m16n8k16.row.col.f32.bf16.bf16.f32 "
        "{%0,%1,%2,%3}, {%4,%5,%6,%7}, {%8,%9}, {%0,%1,%2,%3};\n"
        : "+f"(c[0]), "+f"(c[1]), "+f"(c[2]), "+f"(c[3])
        : "r"(a[0]), "r"(a[1]), "r"(a[2]), "r"(a[3]), "r"(b[0]), "r"(b[1]));
}

__device__ __forceinline__ void ldsm_x4(uint32_t& r0, uint32_t& r1, uint32_t& r2, uint32_t& r3,
                                        const void* p) {
    uint32_t a = (uint32_t)__cvta_generic_to_shared(p);
    asm volatile("ldmatrix.sync.aligned.m8n8.x4.shared.b16 {%0,%1,%2,%3}, [%4];"
                 : "=r"(r0), "=r"(r1), "=r"(r2), "=r"(r3) : "r"(a));
}
__device__ __forceinline__ void ldsm_x4_t(uint32_t& r0, uint32_t& r1, uint32_t& r2, uint32_t& r3,
                                          const void* p) {
    uint32_t a = (uint32_t)__cvta_generic_to_shared(p);
    asm volatile("ldmatrix.sync.aligned.m8n8.x4.trans.shared.b16 {%0,%1,%2,%3}, [%4];"
                 : "=r"(r0), "=r"(r1), "=r"(r2), "=r"(r3) : "r"(a));
}

__device__ __forceinline__ void cp16(void* dst, const void* src) {
    uint32_t d = (uint32_t)__cvta_generic_to_shared(dst);
    asm volatile("cp.async.cg.shared.global [%0], [%1], 16;\n" :: "r"(d), "l"(src));
}
__device__ __forceinline__ void cp_commit() {
    asm volatile("cp.async.commit_group;\n");
}
template<int NPEND> __device__ __forceinline__ void cp_wait() {
    asm volatile("cp.async.wait_group %0;\n" :: "n"(NPEND));
}

// ---------------------------------------------------------------------------
// Kernel 0: w1[r] = W[r,:]·a[:F],  w2[r] = W[r,:]·a[F:]   (W @ a, row dots)
// ---------------------------------------------------------------------------
__global__ void k_wa(const float* __restrict__ W, const float* __restrict__ a) {
    const int r = (blockIdx.x * blockDim.x + threadIdx.x) >> 5;   // 0..255
    const int lane = threadIdx.x & 31;
    if (r >= F_) return;
    const float* row = W + (size_t)r * F_;
    float s1 = 0.f, s2 = 0.f;
    #pragma unroll
    for (int f = lane; f < F_; f += 32) {
        float w = row[f];
        s1 = fmaf(w, a[f],      s1);
        s2 = fmaf(w, a[F_ + f], s2);
    }
    #pragma unroll
    for (int o = 16; o; o >>= 1) {
        s1 += __shfl_xor_sync(0xffffffffu, s1, o);
        s2 += __shfl_xor_sync(0xffffffffu, s2, o);
    }
    if (lane == 0) { g_w1[r] = s1; g_w2[r] = s2; }
}

// ---------------------------------------------------------------------------
// Kernel E: e1[r] = h[r,:]·w1, e2[r] = h[r,:]·w2   (one warp per row, exact)
// ---------------------------------------------------------------------------
__global__ void k_rowdots(const float* __restrict__ h) {
    const int gwarp = (blockIdx.x * blockDim.x + threadIdx.x) >> 5;
    const int lane = threadIdx.x & 31;
    if (gwarp >= ROWS) return;
    const float4* row = (const float4*)(h + (size_t)gwarp * F_);
    const float4* w1v = (const float4*)g_w1;
    const float4* w2v = (const float4*)g_w2;
    float s1 = 0.f, s2 = 0.f;
    #pragma unroll
    for (int f4 = lane; f4 < F_ / 4; f4 += 32) {
        float4 v = row[f4], w1 = w1v[f4], w2 = w2v[f4];
        s1 = fmaf(v.x, w1.x, fmaf(v.y, w1.y, fmaf(v.z, w1.z, fmaf(v.w, w1.w, s1))));
        s2 = fmaf(v.x, w2.x, fmaf(v.y, w2.y, fmaf(v.z, w2.z, fmaf(v.w, w2.w, s2))));
    }
    #pragma unroll
    for (int o = 16; o; o >>= 1) {
        s1 += __shfl_xor_sync(0xffffffffu, s1, o);
        s2 += __shfl_xor_sync(0xffffffffu, s2, o);
    }
    if (lane == 0) { g_e1[gwarp] = s1; g_e2[gwarp] = s2; }
}

// ---------------------------------------------------------------------------
// Kernel 1: Whb(bf16) = h @ W via single-pass TF32 MMA (tile 128x128x32).
// ---------------------------------------------------------------------------
#define STAGE_FLOATS 8960
#define A_OFF 0
#define B_OFF 4608
#define SMEM_BYTES_K1 (2 * STAGE_FLOATS * 4)   // 71680

__global__ __launch_bounds__(256, 2) void k_gemm_wh(const float* __restrict__ h,
                                                    const float* __restrict__ W) {
    extern __shared__ float dsm[];
    const int bx = blockIdx.x;
    const int by = blockIdx.y;
    const int tid = threadIdx.x;
    const int lane = tid & 31, wid = tid >> 5;
    const int warp_m = wid & 3, warp_n = wid >> 2;
    const int gid = lane >> 2, tig = lane & 3;

    const float* A  = h + (size_t)(by * 128) * F_;
    const float* Bg = W + bx * 128;

    float acc[2][8][4];
    #pragma unroll
    for (int mt = 0; mt < 2; mt++)
        #pragma unroll
        for (int j = 0; j < 8; j++)
            #pragma unroll
            for (int q = 0; q < 4; q++) acc[mt][j][q] = 0.f;

    {
        float* As = dsm + A_OFF;
        float* Bs = dsm + B_OFF;
        #pragma unroll
        for (int i = 0; i < 4; i++) {
            int flat = tid + i * 256, row = flat >> 3, c4 = flat & 7;
            cp16(&As[row * 36 + c4 * 4], A + (size_t)row * F_ + c4 * 4);
        }
        #pragma unroll
        for (int i = 0; i < 4; i++) {
            int flat = tid + i * 256, kr = flat >> 5, c4 = flat & 31;
            cp16(&Bs[kr * 136 + c4 * 4], Bg + (size_t)kr * F_ + c4 * 4);
        }
        cp_commit();
    }

    const int NT = F_ / 32;   // 8
    for (int kt = 0; kt < NT; kt++) {
        const int cur = kt & 1;
        if (kt + 1 < NT) {
            const int k0 = (kt + 1) * 32;
            float* As = dsm + (1 - cur) * STAGE_FLOATS + A_OFF;
            float* Bs = dsm + (1 - cur) * STAGE_FLOATS + B_OFF;
            #pragma unroll
            for (int i = 0; i < 4; i++) {
                int flat = tid + i * 256, row = flat >> 3, c4 = flat & 7;
                cp16(&As[row * 36 + c4 * 4], A + (size_t)row * F_ + k0 + c4 * 4);
            }
            #pragma unroll
            for (int i = 0; i < 4; i++) {
                int flat = tid + i * 256, kr = flat >> 5, c4 = flat & 31;
                cp16(&Bs[kr * 136 + c4 * 4], Bg + (size_t)(k0 + kr) * F_ + c4 * 4);
            }
            cp_commit();
            cp_wait<1>();
        } else {
            cp_wait<0>();
        }
        __syncthreads();

        const float* As = dsm + cur * STAGE_FLOATS + A_OFF;
        const float* Bs = dsm + cur * STAGE_FLOATS + B_OFF;

        #pragma unroll
        for (int kk = 0; kk < 32; kk += 8) {
            uint32_t afr[2][4];
            #pragma unroll
            for (int mt = 0; mt < 2; mt++) {
                int r = warp_m * 32 + mt * 16 + gid;
                afr[mt][0] = __float_as_uint(As[ r      * 36 + kk + tig    ]);
                afr[mt][1] = __float_as_uint(As[(r + 8) * 36 + kk + tig    ]);
                afr[mt][2] = __float_as_uint(As[ r      * 36 + kk + tig + 4]);
                afr[mt][3] = __float_as_uint(As[(r + 8) * 36 + kk + tig + 4]);
            }
            uint32_t bfr[8][2];
            #pragma unroll
            for (int j = 0; j < 8; j++) {
                int n = warp_n * 64 + j * 8 + gid;
                bfr[j][0] = __float_as_uint(Bs[(kk + tig    ) * 136 + n]);
                bfr[j][1] = __float_as_uint(Bs[(kk + tig + 4) * 136 + n]);
            }
            #pragma unroll
            for (int mt = 0; mt < 2; mt++)
                #pragma unroll
                for (int j = 0; j < 8; j++)
                    mma_tf32(acc[mt][j], afr[mt], bfr[j]);
        }
        __syncthreads();
    }

    #pragma unroll
    for (int mt = 0; mt < 2; mt++) {
        #pragma unroll
        for (int j = 0; j < 8; j++) {
            const int m0 = by * 128 + warp_m * 32 + mt * 16 + gid;
            const int n  = bx * 128 + warp_n * 64 + j * 8 + tig * 2;
            *(__nv_bfloat162*)(g_Whb + (size_t) m0      * F_ + n) =
                __floats2bfloat162_rn(acc[mt][j][0], acc[mt][j][1]);
            *(__nv_bfloat162*)(g_Whb + (size_t)(m0 + 8) * F_ + n) =
                __floats2bfloat162_rn(acc[mt][j][2], acc[mt][j][3]);
        }
    }
}

// ---------------------------------------------------------------------------
// Kernel 3: masked leaky-relu + softmax — register-resident, no smem staging.
// Each thread owns 8 elements (2 x float4). Writes fp32 att + bf16 copy.
// ---------------------------------------------------------------------------
__global__ __launch_bounds__(256) void k_softmax(const int* __restrict__ adj,
                                                 float* __restrict__ att) {
    const int r = blockIdx.x;            // 0 .. ROWS-1
    const int b = r >> 11;
    __shared__ float red[8];

    const int4*   arow4 = (const int4*)(adj + (size_t)r * N_);
    const float4* e2b4  = (const float4*)(g_e2 + b * N_);
    const float E1 = g_e1[r];
    const int tid = threadIdx.x, lane = tid & 31, wid = tid >> 5;

    const int m4a = tid;            // first float4 group
    const int m4b = tid + 256;      // second float4 group

    int4   ad0 = arow4[m4a], ad1 = arow4[m4b];
    float4 e20 = e2b4[m4a],  e21 = e2b4[m4b];

    float v[8];
    {
        float x;
        x = E1 + e20.x; x = x > 0.f ? x : 0.2f * x; v[0] = ad0.x > 0 ? __expf(x) : 0.f;
        x = E1 + e20.y; x = x > 0.f ? x : 0.2f * x; v[1] = ad0.y > 0 ? __expf(x) : 0.f;
        x = E1 + e20.z; x = x > 0.f ? x : 0.2f * x; v[2] = ad0.z > 0 ? __expf(x) : 0.f;
        x = E1 + e20.w; x = x > 0.f ? x : 0.2f * x; v[3] = ad0.w > 0 ? __expf(x) : 0.f;
        x = E1 + e21.x; x = x > 0.f ? x : 0.2f * x; v[4] = ad1.x > 0 ? __expf(x) : 0.f;
        x = E1 + e21.y; x = x > 0.f ? x : 0.2f * x; v[5] = ad1.y > 0 ? __expf(x) : 0.f;
        x = E1 + e21.z; x = x > 0.f ? x : 0.2f * x; v[6] = ad1.z > 0 ? __expf(x) : 0.f;
        x = E1 + e21.w; x = x > 0.f ? x : 0.2f * x; v[7] = ad1.w > 0 ? __expf(x) : 0.f;
    }
    float lsum = ((v[0] + v[1]) + (v[2] + v[3])) + ((v[4] + v[5]) + (v[6] + v[7]));
    #pragma unroll
    for (int o = 16; o; o >>= 1) lsum += __shfl_xor_sync(0xffffffffu, lsum, o);
    if (lane == 0) red[wid] = lsum;
    __syncthreads();
    if (tid == 0) {
        float t = 0.f;
        #pragma unroll
        for (int i = 0; i < 8; i++) t += red[i];
        red[0] = 1.0f / t;
    }
    __syncthreads();
    const float inv = red[0];

    float4* orow4 = (float4*)(att + (size_t)r * N_);
    __nv_bfloat162* brow2 = (__nv_bfloat162*)(g_att_bf + (size_t)r * N_);
    float4 o0 = make_float4(v[0] * inv, v[1] * inv, v[2] * inv, v[3] * inv);
    float4 o1 = make_float4(v[4] * inv, v[5] * inv, v[6] * inv, v[7] * inv);
    orow4[m4a] = o0;
    orow4[m4b] = o1;
    brow2[m4a * 2    ] = __floats2bfloat162_rn(o0.x, o0.y);
    brow2[m4a * 2 + 1] = __floats2bfloat162_rn(o0.z, o0.w);
    brow2[m4b * 2    ] = __floats2bfloat162_rn(o1.x, o1.y);
    brow2[m4b * 2 + 1] = __floats2bfloat162_rn(o1.z, o1.w);
}

// ---------------------------------------------------------------------------
// Kernel 4: h_prime = attention @ Wh, bf16 m16n8k16 mma.sync.
//   A = g_att_bf [m][k] (ldmatrix.x4),  B = g_Whb [k][n] (ldmatrix.x4.trans).
//   Tile 128x128x32, 3-stage cp.async ring, ONE syncthreads per chunk.
//   Epilogue: out = h + elu(h_prime).
// ---------------------------------------------------------------------------
#define HSTRIDE 40                        // A smem row: 32 bf16 + 8 pad (80 B)
#define BSTRIDE_H 136                     // B smem row: 128 bf16 + 8 pad (272 B)
#define A_ELEMS (128 * HSTRIDE)           // 5120
#define STAGE_H (A_ELEMS + 32 * BSTRIDE_H)   // 5120 + 4352 = 9472 bf16
#define K4_STAGES 3
#define SMEM_BYTES_K4 (K4_STAGES * STAGE_H * 2)   // 56832 B

__device__ __forceinline__ void k4_load_stage(__nv_bfloat16* stage,
                                              const __nv_bfloat16* A,
                                              const __nv_bfloat16* Bw,
                                              int k0, int tid) {
    __nv_bfloat16* As = stage;
    __nv_bfloat16* Bs = stage + A_ELEMS;
    #pragma unroll
    for (int i = 0; i < 2; i++) {
        int flat = tid + i * 256, row = flat >> 2, c = flat & 3;
        cp16(&As[row * HSTRIDE + c * 8], A + (size_t)row * N_ + k0 + c * 8);
    }
    #pragma unroll
    for (int i = 0; i < 2; i++) {
        int flat = tid + i * 256, kr = flat >> 4, c = flat & 15;
        cp16(&Bs[kr * BSTRIDE_H + c * 8], Bw + (size_t)(k0 + kr) * F_ + c * 8);
    }
}

__global__ __launch_bounds__(256, 2) void k_gemm_av_bf16(const float* __restrict__ h,
                                                         float* __restrict__ out) {
    extern __shared__ __nv_bfloat16 hsm[];
    const int bz = blockIdx.z;
    const int bx = blockIdx.x;   // 0..1 (n tile of 128)
    const int by = blockIdx.y;   // 0..15 (m tile of 128)
    const int tid = threadIdx.x;
    const int lane = tid & 31, wid = tid >> 5;
    const int warp_m = wid & 3, warp_n = wid >> 2;
    const int gid = lane >> 2, tig = lane & 3;

    const __nv_bfloat16* A  = g_att_bf + (size_t)bz * N_ * N_ + (size_t)(by * 128) * N_;
    const __nv_bfloat16* Bw = g_Whb   + (size_t)bz * N_ * F_ + bx * 128;

    float acc[2][8][4];
    #pragma unroll
    for (int mt = 0; mt < 2; mt++)
        #pragma unroll
        for (int j = 0; j < 8; j++)
            #pragma unroll
            for (int q = 0; q < 4; q++) acc[mt][j][q] = 0.f;

    // prologue: stages 0,1 = chunks 0,1
    k4_load_stage(hsm,            A, Bw,  0, tid); cp_commit();
    k4_load_stage(hsm + STAGE_H,  A, Bw, 32, tid); cp_commit();

    // ldmatrix lane offsets
    const int a_mat = lane >> 3, a_r = lane & 7;
    const int a_row_off = ((a_mat & 1) << 3) + a_r;     // + mt*16 + warp_m*32
    const int a_k_off   = (a_mat >> 1) << 3;            // + kk
    const int b_k_lane  = lane & 15;                    // k rows kk..kk+15
    const int b_n_half  = (lane >> 4) << 3;             // +8 cols for lanes 16..31

    const int NT = N_ / 32;   // 64
    int s = 0;
    for (int kt = 0; kt < NT; kt++) {
        cp_wait<1>();            // chunk kt resident
        __syncthreads();         // all threads see it; also protects stage reuse

        if (kt + 2 < NT) {
            int sn = s + 2; if (sn >= K4_STAGES) sn -= K4_STAGES;
            k4_load_stage(hsm + sn * STAGE_H, A, Bw, (kt + 2) * 32, tid);
        }
        cp_commit();

        const __nv_bfloat16* As = hsm + s * STAGE_H;
        const __nv_bfloat16* Bs = As + A_ELEMS;

        #pragma unroll
        for (int kk = 0; kk < 32; kk += 16) {
            uint32_t af[2][4];
            #pragma unroll
            for (int mt = 0; mt < 2; mt++) {
                const __nv_bfloat16* p =
                    As + (warp_m * 32 + mt * 16 + a_row_off) * HSTRIDE + kk + a_k_off;
                ldsm_x4(af[mt][0], af[mt][1], af[mt][2], af[mt][3], p);
            }
            uint32_t bf[8][2];
            #pragma unroll
            for (int jp = 0; jp < 4; jp++) {     // pairs of n-groups: x4.trans
                const __nv_bfloat16* p =
                    Bs + (kk + b_k_lane) * BSTRIDE_H + warp_n * 64 + jp * 16 + b_n_half;
                ldsm_x4_t(bf[2*jp][0], bf[2*jp][1], bf[2*jp+1][0], bf[2*jp+1][1], p);
            }
            #pragma unroll
            for (int mt = 0; mt < 2; mt++)
                #pragma unroll
                for (int j = 0; j < 8; j++)
                    mma_bf16(acc[mt][j], af[mt], bf[j]);
        }
        // advance ring
        if (++s >= K4_STAGES) s = 0;
        __syncthreads();   // compute done before next iter's load overwrites s+2 (==s-1)
    }

    // epilogue: out = h + elu(h_prime)
    const size_t base = (size_t)bz * N_ * F_;
    #pragma unroll
    for (int mt = 0; mt < 2; mt++) {
        #pragma unroll
        for (int j = 0; j < 8; j++) {
            const int m0 = by * 128 + warp_m * 32 + mt * 16 + gid;
            const int n  = bx * 128 + warp_n * 64 + j * 8 + tig * 2;
            {
                const size_t idx = base + (size_t)m0 * F_ + n;
                float c0 = acc[mt][j][0], c1 = acc[mt][j][1];
                float e0 = c0 > 0.f ? c0 : expm1f(c0);
                float e1 = c1 > 0.f ? c1 : expm1f(c1);
                float2 hv = *(const float2*)(h + idx);
                *(float2*)(out + idx) = make_float2(hv.x + e0, hv.y + e1);
            }
            {
                const size_t idx = base + (size_t)(m0 + 8) * F_ + n;
                float c2 = acc[mt][j][2], c3 = acc[mt][j][3];
                float e2 = c2 > 0.f ? c2 : expm1f(c2);
                float e3 = c3 > 0.f ? c3 : expm1f(c3);
                float2 hv = *(const float2*)(h + idx);
                *(float2*)(out + idx) = make_float2(hv.x + e2, hv.y + e3);
            }
        }
    }
}

// ---------------------------------------------------------------------------
extern "C" void kernel_launch(void* const* d_in, const int* in_sizes, int n_in,
                              void* d_out, int out_size) {
    const float* h   = (const float*)d_in[0];
    const int*   adj = (const int*)  d_in[1];
    const float* W   = (const float*)d_in[2];
    const float* a   = (const float*)d_in[3];
    float* out = (float*)d_out;
    float* att = out + OUT_ELEMS;

    cudaFuncSetAttribute(k_gemm_wh,      cudaFuncAttributeMaxDynamicSharedMemorySize, SMEM_BYTES_K1);
    cudaFuncSetAttribute(k_gemm_av_bf16, cudaFuncAttributeMaxDynamicSharedMemorySize, SMEM_BYTES_K4);

    // 0. w1/w2 = W @ a  (row dots; exact)
    k_wa<<<F_ / 8, 256>>>(W, a);
    // E. e1/e2 = h @ w1/w2  (exact fp32 scores)
    k_rowdots<<<ROWS / 8, 256>>>(h);
    // 1. Whb(bf16) = h @ W  (single-pass tf32)
    k_gemm_wh<<<dim3(2, ROWS / 128), 256, SMEM_BYTES_K1>>>(h, W);
    // 3. masked softmax -> attention fp32 (d_out) + bf16 scratch (register-resident)
    k_softmax<<<ROWS, 256>>>(adj, att);
    // 4. h_prime = attention @ Wh (bf16 mma.sync, 3-stage) ; out = h + elu(h_prime)
    k_gemm_av_bf16<<<dim3(2, N_ / 128, B_), 256, SMEM_BYTES_K4>>>(h, out);
}

// round 9
// speedup vs baseline: 7.1508x; 1.0796x over previous
#include <cuda_runtime.h>
#include <cuda_bf16.h>
#include <math.h>
#include <stdint.h>

// Problem constants
#define B_  8
#define N_  2048
#define F_  256
#define ROWS (B_ * N_)            // 16384
#define OUT_ELEMS ((size_t)B_ * N_ * F_)   // 4,194,304

// Scratch (device globals — no allocation allowed)
__device__ __nv_bfloat16 g_Whb[(size_t)B_ * N_ * F_];        // 8 MB bf16 [b][node m][feat f]
__device__ __nv_bfloat16 g_att_bf[(size_t)B_ * N_ * N_];     // 67 MB bf16 [b][n][m]
__device__ __align__(16) float g_e1[ROWS];
__device__ __align__(16) float g_e2[ROWS];
__device__ __align__(16) float g_w1[F_];
__device__ __align__(16) float g_w2[F_];

// ---------------------------------------------------------------------------
// MMA / ldmatrix / cp.async helpers
// ---------------------------------------------------------------------------
__device__ __forceinline__ void mma_tf32(float* c, const uint32_t* a, const uint32_t* b) {
    asm volatile(
        "mma.sync.aligned.m16n8k8.row.col.f32.tf32.tf32.f32 "
        "{%0,%1,%2,%3}, {%4,%5,%6,%7}, {%8,%9}, {%0,%1,%2,%3};\n"
        : "+f"(c[0]), "+f"(c[1]), "+f"(c[2]), "+f"(c[3])
        : "r"(a[0]), "r"(a[1]), "r"(a[2]), "r"(a[3]), "r"(b[0]), "r"(b[1]));
}

__device__ __forceinline__ void mma_bf16(float* c, const uint32_t* a, const uint32_t* b) {
    asm volatile(
        "mma.sync.aligned.m16n8k16.row.col.f32.bf16.bf16.f32 "
        "{%0,%1,%2,%3}, {%4,%5,%6,%7}, {%8,%9}, {%0,%1,%2,%3};\n"
        : "+f"(c[0]), "+f"(c[1]), "+f"(c[2]), "+f"(c[3])
        : "r"(a[0]), "r"(a[1]), "r"(a[2]), "r"(a[3]), "r"(b[0]), "r"(b[1]));
}

__device__ __forceinline__ void ldsm_x4(uint32_t& r0, uint32_t& r1, uint32_t& r2, uint32_t& r3,
                                        const void* p) {
    uint32_t a = (uint32_t)__cvta_generic_to_shared(p);
    asm volatile("ldmatrix.sync.aligned.m8n8.x4.shared.b16 {%0,%1,%2,%3}, [%4];"
                 : "=r"(r0), "=r"(r1), "=r"(r2), "=r"(r3) : "r"(a));
}
__device__ __forceinline__ void ldsm_x4_t(uint32_t& r0, uint32_t& r1, uint32_t& r2, uint32_t& r3,
                                          const void* p) {
    uint32_t a = (uint32_t)__cvta_generic_to_shared(p);
    asm volatile("ldmatrix.sync.aligned.m8n8.x4.trans.shared.b16 {%0,%1,%2,%3}, [%4];"
                 : "=r"(r0), "=r"(r1), "=r"(r2), "=r"(r3) : "r"(a));
}

__device__ __forceinline__ void cp16(void* dst, const void* src) {
    uint32_t d = (uint32_t)__cvta_generic_to_shared(dst);
    asm volatile("cp.async.cg.shared.global [%0], [%1], 16;\n" :: "r"(d), "l"(src));
}
__device__ __forceinline__ void cp_commit() {
    asm volatile("cp.async.commit_group;\n");
}
template<int NPEND> __device__ __forceinline__ void cp_wait() {
    asm volatile("cp.async.wait_group %0;\n" :: "n"(NPEND));
}

// ---------------------------------------------------------------------------
// Kernel 0: w1[r] = W[r,:]·a[:F],  w2[r] = W[r,:]·a[F:]   (W @ a, row dots)
// ---------------------------------------------------------------------------
__global__ void k_wa(const float* __restrict__ W, const float* __restrict__ a) {
    const int r = (blockIdx.x * blockDim.x + threadIdx.x) >> 5;   // 0..255
    const int lane = threadIdx.x & 31;
    if (r >= F_) return;
    const float* row = W + (size_t)r * F_;
    float s1 = 0.f, s2 = 0.f;
    #pragma unroll
    for (int f = lane; f < F_; f += 32) {
        float w = row[f];
        s1 = fmaf(w, a[f],      s1);
        s2 = fmaf(w, a[F_ + f], s2);
    }
    #pragma unroll
    for (int o = 16; o; o >>= 1) {
        s1 += __shfl_xor_sync(0xffffffffu, s1, o);
        s2 += __shfl_xor_sync(0xffffffffu, s2, o);
    }
    if (lane == 0) { g_w1[r] = s1; g_w2[r] = s2; }
}

// ---------------------------------------------------------------------------
// Kernel E: e1[r] = h[r,:]·w1, e2[r] = h[r,:]·w2   (one warp per row, exact)
// ---------------------------------------------------------------------------
__global__ void k_rowdots(const float* __restrict__ h) {
    const int gwarp = (blockIdx.x * blockDim.x + threadIdx.x) >> 5;
    const int lane = threadIdx.x & 31;
    if (gwarp >= ROWS) return;
    const float4* row = (const float4*)(h + (size_t)gwarp * F_);
    const float4* w1v = (const float4*)g_w1;
    const float4* w2v = (const float4*)g_w2;
    float s1 = 0.f, s2 = 0.f;
    #pragma unroll
    for (int f4 = lane; f4 < F_ / 4; f4 += 32) {
        float4 v = row[f4], w1 = w1v[f4], w2 = w2v[f4];
        s1 = fmaf(v.x, w1.x, fmaf(v.y, w1.y, fmaf(v.z, w1.z, fmaf(v.w, w1.w, s1))));
        s2 = fmaf(v.x, w2.x, fmaf(v.y, w2.y, fmaf(v.z, w2.z, fmaf(v.w, w2.w, s2))));
    }
    #pragma unroll
    for (int o = 16; o; o >>= 1) {
        s1 += __shfl_xor_sync(0xffffffffu, s1, o);
        s2 += __shfl_xor_sync(0xffffffffu, s2, o);
    }
    if (lane == 0) { g_e1[gwarp] = s1; g_e2[gwarp] = s2; }
}

// ---------------------------------------------------------------------------
// Kernel 1: Whb(bf16) = h @ W via single-pass TF32 MMA (tile 128x128x32).
// ---------------------------------------------------------------------------
#define STAGE_FLOATS 8960
#define A_OFF 0
#define B_OFF 4608
#define SMEM_BYTES_K1 (2 * STAGE_FLOATS * 4)   // 71680

__global__ __launch_bounds__(256, 2) void k_gemm_wh(const float* __restrict__ h,
                                                    const float* __restrict__ W) {
    extern __shared__ float dsm[];
    const int bx = blockIdx.x;
    const int by = blockIdx.y;
    const int tid = threadIdx.x;
    const int lane = tid & 31, wid = tid >> 5;
    const int warp_m = wid & 3, warp_n = wid >> 2;
    const int gid = lane >> 2, tig = lane & 3;

    const float* A  = h + (size_t)(by * 128) * F_;
    const float* Bg = W + bx * 128;

    float acc[2][8][4];
    #pragma unroll
    for (int mt = 0; mt < 2; mt++)
        #pragma unroll
        for (int j = 0; j < 8; j++)
            #pragma unroll
            for (int q = 0; q < 4; q++) acc[mt][j][q] = 0.f;

    {
        float* As = dsm + A_OFF;
        float* Bs = dsm + B_OFF;
        #pragma unroll
        for (int i = 0; i < 4; i++) {
            int flat = tid + i * 256, row = flat >> 3, c4 = flat & 7;
            cp16(&As[row * 36 + c4 * 4], A + (size_t)row * F_ + c4 * 4);
        }
        #pragma unroll
        for (int i = 0; i < 4; i++) {
            int flat = tid + i * 256, kr = flat >> 5, c4 = flat & 31;
            cp16(&Bs[kr * 136 + c4 * 4], Bg + (size_t)kr * F_ + c4 * 4);
        }
        cp_commit();
    }

    const int NT = F_ / 32;   // 8
    for (int kt = 0; kt < NT; kt++) {
        const int cur = kt & 1;
        if (kt + 1 < NT) {
            const int k0 = (kt + 1) * 32;
            float* As = dsm + (1 - cur) * STAGE_FLOATS + A_OFF;
            float* Bs = dsm + (1 - cur) * STAGE_FLOATS + B_OFF;
            #pragma unroll
            for (int i = 0; i < 4; i++) {
                int flat = tid + i * 256, row = flat >> 3, c4 = flat & 7;
                cp16(&As[row * 36 + c4 * 4], A + (size_t)row * F_ + k0 + c4 * 4);
            }
            #pragma unroll
            for (int i = 0; i < 4; i++) {
                int flat = tid + i * 256, kr = flat >> 5, c4 = flat & 31;
                cp16(&Bs[kr * 136 + c4 * 4], Bg + (size_t)(k0 + kr) * F_ + c4 * 4);
            }
            cp_commit();
            cp_wait<1>();
        } else {
            cp_wait<0>();
        }
        __syncthreads();

        const float* As = dsm + cur * STAGE_FLOATS + A_OFF;
        const float* Bs = dsm + cur * STAGE_FLOATS + B_OFF;

        #pragma unroll
        for (int kk = 0; kk < 32; kk += 8) {
            uint32_t afr[2][4];
            #pragma unroll
            for (int mt = 0; mt < 2; mt++) {
                int r = warp_m * 32 + mt * 16 + gid;
                afr[mt][0] = __float_as_uint(As[ r      * 36 + kk + tig    ]);
                afr[mt][1] = __float_as_uint(As[(r + 8) * 36 + kk + tig    ]);
                afr[mt][2] = __float_as_uint(As[ r      * 36 + kk + tig + 4]);
                afr[mt][3] = __float_as_uint(As[(r + 8) * 36 + kk + tig + 4]);
            }
            uint32_t bfr[8][2];
            #pragma unroll
            for (int j = 0; j < 8; j++) {
                int n = warp_n * 64 + j * 8 + gid;
                bfr[j][0] = __float_as_uint(Bs[(kk + tig    ) * 136 + n]);
                bfr[j][1] = __float_as_uint(Bs[(kk + tig + 4) * 136 + n]);
            }
            #pragma unroll
            for (int mt = 0; mt < 2; mt++)
                #pragma unroll
                for (int j = 0; j < 8; j++)
                    mma_tf32(acc[mt][j], afr[mt], bfr[j]);
        }
        __syncthreads();
    }

    #pragma unroll
    for (int mt = 0; mt < 2; mt++) {
        #pragma unroll
        for (int j = 0; j < 8; j++) {
            const int m0 = by * 128 + warp_m * 32 + mt * 16 + gid;
            const int n  = bx * 128 + warp_n * 64 + j * 8 + tig * 2;
            *(__nv_bfloat162*)(g_Whb + (size_t) m0      * F_ + n) =
                __floats2bfloat162_rn(acc[mt][j][0], acc[mt][j][1]);
            *(__nv_bfloat162*)(g_Whb + (size_t)(m0 + 8) * F_ + n) =
                __floats2bfloat162_rn(acc[mt][j][2], acc[mt][j][3]);
        }
    }
}

// ---------------------------------------------------------------------------
// Kernel 3: masked leaky-relu + softmax — register-resident, no smem staging.
// ---------------------------------------------------------------------------
__global__ __launch_bounds__(256) void k_softmax(const int* __restrict__ adj,
                                                 float* __restrict__ att) {
    const int r = blockIdx.x;            // 0 .. ROWS-1
    const int b = r >> 11;
    __shared__ float red[8];

    const int4*   arow4 = (const int4*)(adj + (size_t)r * N_);
    const float4* e2b4  = (const float4*)(g_e2 + b * N_);
    const float E1 = g_e1[r];
    const int tid = threadIdx.x, lane = tid & 31, wid = tid >> 5;

    const int m4a = tid;
    const int m4b = tid + 256;

    int4   ad0 = arow4[m4a], ad1 = arow4[m4b];
    float4 e20 = e2b4[m4a],  e21 = e2b4[m4b];

    float v[8];
    {
        float x;
        x = E1 + e20.x; x = x > 0.f ? x : 0.2f * x; v[0] = ad0.x > 0 ? __expf(x) : 0.f;
        x = E1 + e20.y; x = x > 0.f ? x : 0.2f * x; v[1] = ad0.y > 0 ? __expf(x) : 0.f;
        x = E1 + e20.z; x = x > 0.f ? x : 0.2f * x; v[2] = ad0.z > 0 ? __expf(x) : 0.f;
        x = E1 + e20.w; x = x > 0.f ? x : 0.2f * x; v[3] = ad0.w > 0 ? __expf(x) : 0.f;
        x = E1 + e21.x; x = x > 0.f ? x : 0.2f * x; v[4] = ad1.x > 0 ? __expf(x) : 0.f;
        x = E1 + e21.y; x = x > 0.f ? x : 0.2f * x; v[5] = ad1.y > 0 ? __expf(x) : 0.f;
        x = E1 + e21.z; x = x > 0.f ? x : 0.2f * x; v[6] = ad1.z > 0 ? __expf(x) : 0.f;
        x = E1 + e21.w; x = x > 0.f ? x : 0.2f * x; v[7] = ad1.w > 0 ? __expf(x) : 0.f;
    }
    float lsum = ((v[0] + v[1]) + (v[2] + v[3])) + ((v[4] + v[5]) + (v[6] + v[7]));
    #pragma unroll
    for (int o = 16; o; o >>= 1) lsum += __shfl_xor_sync(0xffffffffu, lsum, o);
    if (lane == 0) red[wid] = lsum;
    __syncthreads();
    if (tid == 0) {
        float t = 0.f;
        #pragma unroll
        for (int i = 0; i < 8; i++) t += red[i];
        red[0] = 1.0f / t;
    }
    __syncthreads();
    const float inv = red[0];

    float4* orow4 = (float4*)(att + (size_t)r * N_);
    __nv_bfloat162* brow2 = (__nv_bfloat162*)(g_att_bf + (size_t)r * N_);
    float4 o0 = make_float4(v[0] * inv, v[1] * inv, v[2] * inv, v[3] * inv);
    float4 o1 = make_float4(v[4] * inv, v[5] * inv, v[6] * inv, v[7] * inv);
    orow4[m4a] = o0;
    orow4[m4b] = o1;
    brow2[m4a * 2    ] = __floats2bfloat162_rn(o0.x, o0.y);
    brow2[m4a * 2 + 1] = __floats2bfloat162_rn(o0.z, o0.w);
    brow2[m4b * 2    ] = __floats2bfloat162_rn(o1.x, o1.y);
    brow2[m4b * 2 + 1] = __floats2bfloat162_rn(o1.z, o1.w);
}

// ---------------------------------------------------------------------------
// Kernel 4: h_prime = attention @ Wh, bf16 m16n8k16 mma.sync.
//   Tile 128x128, K-chunk 64, 3-stage cp.async ring.
//   A stride 72 (144B: 4-bank shift/row, ldmatrix conflict-free),
//   B stride 136 (272B, conflict-free). Epilogue: out = h + elu(h_prime).
// ---------------------------------------------------------------------------
#define KCHUNK 64
#define HSTRIDE 72                        // A smem row: 64 bf16 + 8 pad (144 B)
#define BSTRIDE_H 136                     // B smem row: 128 bf16 + 8 pad (272 B)
#define A_ELEMS (128 * HSTRIDE)           // 9216
#define STAGE_H (A_ELEMS + KCHUNK * BSTRIDE_H)   // 9216 + 8704 = 17920 bf16
#define K4_STAGES 3
#define SMEM_BYTES_K4 (K4_STAGES * STAGE_H * 2)   // 107520 B

__device__ __forceinline__ void k4_load_stage(__nv_bfloat16* stage,
                                              const __nv_bfloat16* A,
                                              const __nv_bfloat16* Bw,
                                              int k0, int tid) {
    __nv_bfloat16* As = stage;
    __nv_bfloat16* Bs = stage + A_ELEMS;
    #pragma unroll
    for (int i = 0; i < 4; i++) {                 // A: 128 rows x 8 x 16B
        int flat = tid + i * 256, row = flat >> 3, c = flat & 7;
        cp16(&As[row * HSTRIDE + c * 8], A + (size_t)row * N_ + k0 + c * 8);
    }
    #pragma unroll
    for (int i = 0; i < 4; i++) {                 // B: 64 rows x 16 x 16B
        int flat = tid + i * 256, kr = flat >> 4, c = flat & 15;
        cp16(&Bs[kr * BSTRIDE_H + c * 8], Bw + (size_t)(k0 + kr) * F_ + c * 8);
    }
}

__global__ __launch_bounds__(256, 2) void k_gemm_av_bf16(const float* __restrict__ h,
                                                         float* __restrict__ out) {
    extern __shared__ __nv_bfloat16 hsm[];
    const int bz = blockIdx.z;
    const int bx = blockIdx.x;   // 0..1 (n tile of 128)
    const int by = blockIdx.y;   // 0..15 (m tile of 128)
    const int tid = threadIdx.x;
    const int lane = tid & 31, wid = tid >> 5;
    const int warp_m = wid & 3, warp_n = wid >> 2;
    const int gid = lane >> 2, tig = lane & 3;

    const __nv_bfloat16* A  = g_att_bf + (size_t)bz * N_ * N_ + (size_t)(by * 128) * N_;
    const __nv_bfloat16* Bw = g_Whb   + (size_t)bz * N_ * F_ + bx * 128;

    float acc[2][8][4];
    #pragma unroll
    for (int mt = 0; mt < 2; mt++)
        #pragma unroll
        for (int j = 0; j < 8; j++)
            #pragma unroll
            for (int q = 0; q < 4; q++) acc[mt][j][q] = 0.f;

    // prologue: stages 0,1 = chunks 0,1
    k4_load_stage(hsm,           A, Bw, 0,      tid); cp_commit();
    k4_load_stage(hsm + STAGE_H, A, Bw, KCHUNK, tid); cp_commit();

    // ldmatrix lane offsets
    const int a_mat = lane >> 3, a_r = lane & 7;
    const int a_row_off = ((a_mat & 1) << 3) + a_r;     // + mt*16 + warp_m*32
    const int a_k_off   = (a_mat >> 1) << 3;            // + kk
    const int b_k_lane  = lane & 15;                    // k rows kk..kk+15
    const int b_n_half  = (lane >> 4) << 3;             // +8 cols for lanes 16..31

    const int NT = N_ / KCHUNK;   // 32
    int s = 0;
    for (int kt = 0; kt < NT; kt++) {
        cp_wait<1>();            // chunk kt resident
        __syncthreads();

        if (kt + 2 < NT) {
            int sn = s + 2; if (sn >= K4_STAGES) sn -= K4_STAGES;
            k4_load_stage(hsm + sn * STAGE_H, A, Bw, (kt + 2) * KCHUNK, tid);
        }
        cp_commit();

        const __nv_bfloat16* As = hsm + s * STAGE_H;
        const __nv_bfloat16* Bs = As + A_ELEMS;

        #pragma unroll
        for (int kk = 0; kk < KCHUNK; kk += 16) {
            uint32_t af[2][4];
            #pragma unroll
            for (int mt = 0; mt < 2; mt++) {
                const __nv_bfloat16* p =
                    As + (warp_m * 32 + mt * 16 + a_row_off) * HSTRIDE + kk + a_k_off;
                ldsm_x4(af[mt][0], af[mt][1], af[mt][2], af[mt][3], p);
            }
            uint32_t bf[8][2];
            #pragma unroll
            for (int jp = 0; jp < 4; jp++) {
                const __nv_bfloat16* p =
                    Bs + (kk + b_k_lane) * BSTRIDE_H + warp_n * 64 + jp * 16 + b_n_half;
                ldsm_x4_t(bf[2*jp][0], bf[2*jp][1], bf[2*jp+1][0], bf[2*jp+1][1], p);
            }
            #pragma unroll
            for (int mt = 0; mt < 2; mt++)
                #pragma unroll
                for (int j = 0; j < 8; j++)
                    mma_bf16(acc[mt][j], af[mt], bf[j]);
        }
        if (++s >= K4_STAGES) s = 0;
        __syncthreads();   // compute done before next iter's load overwrites stage s-1
    }

    // epilogue: out = h + elu(h_prime)
    const size_t base = (size_t)bz * N_ * F_;
    #pragma unroll
    for (int mt = 0; mt < 2; mt++) {
        #pragma unroll
        for (int j = 0; j < 8; j++) {
            const int m0 = by * 128 + warp_m * 32 + mt * 16 + gid;
            const int n  = bx * 128 + warp_n * 64 + j * 8 + tig * 2;
            {
                const size_t idx = base + (size_t)m0 * F_ + n;
                float c0 = acc[mt][j][0], c1 = acc[mt][j][1];
                float e0 = c0 > 0.f ? c0 : expm1f(c0);
                float e1 = c1 > 0.f ? c1 : expm1f(c1);
                float2 hv = *(const float2*)(h + idx);
                *(float2*)(out + idx) = make_float2(hv.x + e0, hv.y + e1);
            }
            {
                const size_t idx = base + (size_t)(m0 + 8) * F_ + n;
                float c2 = acc[mt][j][2], c3 = acc[mt][j][3];
                float e2 = c2 > 0.f ? c2 : expm1f(c2);
                float e3 = c3 > 0.f ? c3 : expm1f(c3);
                float2 hv = *(const float2*)(h + idx);
                *(float2*)(out + idx) = make_float2(hv.x + e2, hv.y + e3);
            }
        }
    }
}

// ---------------------------------------------------------------------------
extern "C" void kernel_launch(void* const* d_in, const int* in_sizes, int n_in,
                              void* d_out, int out_size) {
    const float* h   = (const float*)d_in[0];
    const int*   adj = (const int*)  d_in[1];
    const float* W   = (const float*)d_in[2];
    const float* a   = (const float*)d_in[3];
    float* out = (float*)d_out;
    float* att = out + OUT_ELEMS;

    cudaFuncSetAttribute(k_gemm_wh,      cudaFuncAttributeMaxDynamicSharedMemorySize, SMEM_BYTES_K1);
    cudaFuncSetAttribute(k_gemm_av_bf16, cudaFuncAttributeMaxDynamicSharedMemorySize, SMEM_BYTES_K4);

    // Fork a side stream so k_gemm_wh (independent) overlaps the softmax path.
    // Host-side stream/event objects only — no device memory. Not destroyed
    // (destroying a capture-forked stream before EndCapture invalidates capture;
    // kernel_launch runs exactly twice outside timing, so the leak is bounded).
    cudaStream_t s2;
    cudaStreamCreateWithFlags(&s2, cudaStreamNonBlocking);
    cudaEvent_t eFork, eJoin;
    cudaEventCreateWithFlags(&eFork, cudaEventDisableTiming);
    cudaEventCreateWithFlags(&eJoin, cudaEventDisableTiming);

    cudaEventRecord(eFork, 0);
    cudaStreamWaitEvent(s2, eFork, 0);
    // side branch: 1. Whb(bf16) = h @ W  (single-pass tf32)
    k_gemm_wh<<<dim3(2, ROWS / 128), 256, SMEM_BYTES_K1, s2>>>(h, W);
    cudaEventRecord(eJoin, s2);

    // main branch (critical path):
    // 0. w1/w2 = W @ a  (row dots; exact)
    k_wa<<<F_ / 8, 256>>>(W, a);
    // E. e1/e2 = h @ w1/w2  (exact fp32 scores)
    k_rowdots<<<ROWS / 8, 256>>>(h);
    // 3. masked softmax -> attention fp32 (d_out) + bf16 scratch
    k_softmax<<<ROWS, 256>>>(adj, att);

    // join, then 4. h_prime = attention @ Wh ; out = h + elu(h_prime)
    cudaStreamWaitEvent(0, eJoin, 0);
    k_gemm_av_bf16<<<dim3(2, N_ / 128, B_), 256, SMEM_BYTES_K4>>>(h, out);
}